// round 14
// baseline (speedup 1.0000x reference)
#include <cuda_runtime.h>
#include <cuda_bf16.h>
#include <cuda_fp16.h>
#include <math.h>
#include <math_constants.h>
#include <cstdint>

#define BB 2
#define SS 2048
#define DD 1024
#define HH 16
#define DK 64

// ---------------- scratch (allocation-free: __device__ globals) ----------------
__device__ float g_ct[BB*SS*32];
__device__ float g_st[BB*SS*32];
__device__ __half g_xhi[BB*SS*DD], g_xlo[BB*SS*DD];
__device__ __half g_wc[3*DD*DD];                    // Wq|Wk|Wv single fp16
__device__ __half g_wo[DD*DD];                      // Wo single fp16
__device__ __half g_qhi[BB*HH*SS*DK], g_qlo[BB*HH*SS*DK];  // headed, rope'd, *CSC
__device__ __half g_kk[BB*HH*SS*DK];                // headed, rope'd, single
__device__ __half g_vv[BB*HH*SS*DK];                // headed, single
__device__ __half g_abhi[BB*SS*DD], g_ablo[BB*SS*DD];

// ======================= helpers ================================================
__device__ __forceinline__ uint32_t smem_u32(const void* p) {
    uint32_t a;
    asm("{ .reg .u64 t; cvta.to.shared.u64 t, %1; cvt.u32.u64 %0, t; }" : "=r"(a) : "l"(p));
    return a;
}
__device__ __forceinline__ uint32_t pack_h(float a, float b) {
    __half2 h = __floats2half2_rn(a, b);
    return *(uint32_t*)&h;
}
__device__ __forceinline__ void split_pack_h(float a, float b, uint32_t& hi, uint32_t& lo) {
    __half ha = __float2half_rn(a);
    __half hb = __float2half_rn(b);
    hi = (uint32_t)__half_as_ushort(ha) | ((uint32_t)__half_as_ushort(hb) << 16);
    lo = pack_h(a - __half2float(ha), b - __half2float(hb));
}
__device__ __forceinline__ void mma_f16(float c[4], const uint32_t a[4],
                                        uint32_t b0, uint32_t b1) {
    asm volatile(
        "mma.sync.aligned.m16n8k16.row.col.f32.f16.f16.f32 "
        "{%0,%1,%2,%3},{%4,%5,%6,%7},{%8,%9},{%0,%1,%2,%3};"
        : "+f"(c[0]), "+f"(c[1]), "+f"(c[2]), "+f"(c[3])
        : "r"(a[0]), "r"(a[1]), "r"(a[2]), "r"(a[3]), "r"(b0), "r"(b1));
}
__device__ __forceinline__ float exp2a(float x) {
    x = fmaxf(x, -126.0f);
    float z = x + 12582912.0f;
    uint32_t iz = __float_as_uint(z);
    float f = x - (z - 12582912.0f);
    float p = 0.0013333558f;
    p = fmaf(p, f, 0.0096180885f);
    p = fmaf(p, f, 0.0555041087f);
    p = fmaf(p, f, 0.2402265069f);
    p = fmaf(p, f, 0.6931471806f);
    p = fmaf(p, f, 1.0f);
    return __uint_as_float(__float_as_uint(p) + (iz << 23));
}
__device__ __forceinline__ void cp16(uint32_t dst, const void* src) {
    asm volatile("cp.async.ca.shared.global [%0], [%1], 16;" :: "r"(dst), "l"(src));
}
#define CP_COMMIT() asm volatile("cp.async.commit_group;" ::: "memory")
#define CP_WAIT0()  asm volatile("cp.async.wait_group 0;" ::: "memory")
#define CP_WAIT1()  asm volatile("cp.async.wait_group 1;" ::: "memory")
#define LDSM4(d, a) \
    asm volatile("ldmatrix.sync.aligned.m8n8.x4.shared.b16 {%0,%1,%2,%3},[%4];" \
        : "=r"((d)[0]), "=r"((d)[1]), "=r"((d)[2]), "=r"((d)[3]) : "r"(a))
#define LDSM4T(d, a) \
    asm volatile("ldmatrix.sync.aligned.m8n8.x4.trans.shared.b16 {%0,%1,%2,%3},[%4];" \
        : "=r"((d)[0]), "=r"((d)[1]), "=r"((d)[2]), "=r"((d)[3]) : "r"(a))

// ======================= pre-pass conversions ===================================
#define NX4 (BB*SS*DD/4)
#define NW4 (DD*DD/4)
__global__ void cvt_all_kernel(const float* __restrict__ x,  const float* __restrict__ Wq,
                               const float* __restrict__ Wk, const float* __restrict__ Wv,
                               const float* __restrict__ Wo,
                               __half* __restrict__ xhi, __half* __restrict__ xlo,
                               __half* __restrict__ wc, __half* __restrict__ wo)
{
    int idx = blockIdx.x * blockDim.x + threadIdx.x;
    if (idx < NX4) {
        float4 v = *(const float4*)&x[(size_t)idx * 4];
        uint32_t h0, l0, h1, l1;
        split_pack_h(v.x, v.y, h0, l0);
        split_pack_h(v.z, v.w, h1, l1);
        *(uint2*)&xhi[(size_t)idx * 4] = make_uint2(h0, h1);
        *(uint2*)&xlo[(size_t)idx * 4] = make_uint2(l0, l1);
        return;
    }
    const float* src;
    __half* dst;
    int off;
    if (idx < NX4 + NW4)        { src = Wq; dst = wc;             off = idx - NX4; }
    else if (idx < NX4 + 2*NW4) { src = Wk; dst = wc + DD*DD;     off = idx - NX4 - NW4; }
    else if (idx < NX4 + 3*NW4) { src = Wv; dst = wc + 2*DD*DD;   off = idx - NX4 - 2*NW4; }
    else if (idx < NX4 + 4*NW4) { src = Wo; dst = wo;             off = idx - NX4 - 3*NW4; }
    else return;
    float4 v = *(const float4*)&src[(size_t)off * 4];
    *(uint2*)&dst[(size_t)off * 4] = make_uint2(pack_h(v.x, v.y), pack_h(v.z, v.w));
}

// ======================= RoPE table =============================================
__global__ void rope_tab_kernel(const int* __restrict__ tp, float* __restrict__ ct,
                                float* __restrict__ st)
{
    int idx = blockIdx.x * blockDim.x + threadIdx.x;
    if (idx >= BB*SS*32) return;
    int m = idx >> 5;
    int p = idx & 31;
    float inv = powf(10000.0f, -(float)(2*p) * (1.0f/64.0f));
    float freq = (float)tp[m] * inv;
    float sn, cs;
    sincosf(freq, &sn, &cs);
    ct[idx] = cs;
    st[idx] = sn;
}

// ======================= GEMM v6 (round-12, unchanged) ==========================
#define SROW 20
#define SROWB (SROW*4)
#define G5_ARR 2560
#define G5_STAGE (3*G5_ARR)
#define G5_SMEM_BYTES (2*G5_STAGE*4)   // 61440
#define CSCALE (0.125f * 1.44269504088896f)

__global__ __launch_bounds__(128, 2)
void gemm_mma6_kernel(const __half* __restrict__ Ahi, const __half* __restrict__ Alo,
                      const __half* __restrict__ Bh,
                      const float* __restrict__ ct, const float* __restrict__ st,
                      __half* __restrict__ qhi, __half* __restrict__ qlo,
                      __half* __restrict__ kkp, __half* __restrict__ vvp,
                      float* __restrict__ outp, int mode)
{
    extern __shared__ uint32_t su2[];
    const uint32_t sbase = smem_u32(su2);

    const int tid = threadIdx.x;
    const int wid = tid >> 5;
    const int lid = tid & 31;
    const int wm = wid >> 1;
    const int wn = wid & 1;
    const int r  = lid >> 2;
    const int c4 = lid & 3;
    const int i8 = lid & 7;
    const int m8 = lid >> 3;
    const int m0 = blockIdx.y * 128;

    int n0, seg;
    const __half* bp = Bh;
    if (mode == 3) {
        seg = blockIdx.x >> 3;
        n0 = (blockIdx.x & 7) * 128;
        bp += (size_t)seg * DD * DD;
    } else {
        seg = 3;
        n0 = blockIdx.x * 128;
    }

    const int prow = tid >> 2;
    const int pch  = tid & 3;

    float C[4][8][4];
    #pragma unroll
    for (int mt = 0; mt < 4; mt++)
        #pragma unroll
        for (int nt = 0; nt < 8; nt++)
            #pragma unroll
            for (int q = 0; q < 4; q++) C[mt][nt][q] = 0.f;

    auto prefetch = [&](int kt, int st2) {
        const int k0 = kt * 32;
        #pragma unroll
        for (int i = 0; i < 4; i++) {
            int row = prow + i * 32;
            uint32_t d = sbase + (uint32_t)(st2 * G5_STAGE + row * SROW + pch * 4) * 4u;
            size_t goA = (size_t)(m0 + row) * DD + k0 + pch * 8;
            size_t goB = (size_t)(n0 + row) * DD + k0 + pch * 8;
            cp16(d,                Ahi + goA);
            cp16(d + G5_ARR * 4u,  Alo + goA);
            cp16(d + 2u*G5_ARR*4u, bp  + goB);
        }
        CP_COMMIT();
    };

    prefetch(0, 0);

    const uint32_t aLane = (uint32_t)(wm * 64 + i8 + ((m8 & 1) << 3)) * SROWB + ((m8 & 2) << 3);
    const uint32_t bLane = (uint32_t)(wn * 64 + i8 + ((m8 & 2) << 2)) * SROWB + ((m8 & 1) << 4);

    for (int kt = 0; kt < 32; kt++) {
        CP_WAIT0();
        __syncthreads();
        if (kt < 31) prefetch(kt + 1, (kt + 1) & 1);

        const uint32_t stageB = sbase + (uint32_t)((kt & 1) * G5_STAGE) * 4u;
        const uint32_t aHiB = stageB;
        const uint32_t aLoB = stageB + G5_ARR * 4u;
        const uint32_t bB   = stageB + 2u * G5_ARR * 4u;

        #pragma unroll
        for (int kc = 0; kc < 2; kc++) {
            uint32_t bh[4][4];
            #pragma unroll
            for (int p = 0; p < 4; p++)
                LDSM4(bh[p], bB + bLane + p * (16 * SROWB) + kc * 32);
            #pragma unroll
            for (int mt = 0; mt < 4; mt++) {
                uint32_t ah[4], al[4];
                LDSM4(ah, aHiB + aLane + mt * (16 * SROWB) + kc * 32);
                LDSM4(al, aLoB + aLane + mt * (16 * SROWB) + kc * 32);
                #pragma unroll
                for (int p = 0; p < 4; p++) {
                    mma_f16(C[mt][2*p],   ah, bh[p][0], bh[p][1]);
                    mma_f16(C[mt][2*p+1], ah, bh[p][2], bh[p][3]);
                    mma_f16(C[mt][2*p],   al, bh[p][0], bh[p][1]);
                    mma_f16(C[mt][2*p+1], al, bh[p][2], bh[p][3]);
                }
            }
        }
    }

    #pragma unroll
    for (int mt = 0; mt < 4; mt++) {
        const int row0 = m0 + wm * 64 + mt * 16 + r;
        const int row1 = row0 + 8;
        #pragma unroll
        for (int nt = 0; nt < 8; nt++) {
            const int ncol = n0 + wn * 64 + nt * 8 + c4 * 2;
            float v00 = C[mt][nt][0], v01 = C[mt][nt][1];
            float v10 = C[mt][nt][2], v11 = C[mt][nt][3];
            if (seg == 3) {
                *(float2*)&outp[(size_t)row0 * DD + ncol] = make_float2(v00, v01);
                *(float2*)&outp[(size_t)row1 * DD + ncol] = make_float2(v10, v11);
            } else {
                const int h   = ncol >> 6;
                const int dk0 = ncol & 63;
                if (seg < 2) {
                    const int p = dk0 >> 1;
                    float cs0 = ct[(size_t)row0 * 32 + p], sn0 = st[(size_t)row0 * 32 + p];
                    float cs1 = ct[(size_t)row1 * 32 + p], sn1 = st[(size_t)row1 * 32 + p];
                    float t00 = cs0 * v00 - sn0 * v01;
                    float t01 = sn0 * v00 + cs0 * v01;
                    float t10 = cs1 * v10 - sn1 * v11;
                    float t11 = sn1 * v10 + cs1 * v11;
                    v00 = t00; v01 = t01; v10 = t10; v11 = t11;
                    if (seg == 0) { v00 *= CSCALE; v01 *= CSCALE; v10 *= CSCALE; v11 *= CSCALE; }
                }
                const int b0r = row0 >> 11, s0 = row0 & (SS - 1);
                const int b1r = row1 >> 11, s1 = row1 & (SS - 1);
                size_t hb0 = ((size_t)(b0r * HH + h) * SS + s0) * 32 + (dk0 >> 1);
                size_t hb1 = ((size_t)(b1r * HH + h) * SS + s1) * 32 + (dk0 >> 1);
                if (seg == 0) {
                    uint32_t h0, l0, h1, l1;
                    split_pack_h(v00, v01, h0, l0);
                    split_pack_h(v10, v11, h1, l1);
                    ((uint32_t*)qhi)[hb0] = h0;  ((uint32_t*)qlo)[hb0] = l0;
                    ((uint32_t*)qhi)[hb1] = h1;  ((uint32_t*)qlo)[hb1] = l1;
                } else if (seg == 1) {
                    ((uint32_t*)kkp)[hb0] = pack_h(v00, v01);
                    ((uint32_t*)kkp)[hb1] = pack_h(v10, v11);
                } else {
                    ((uint32_t*)vvp)[hb0] = pack_h(v00, v01);
                    ((uint32_t*)vvp)[hb1] = pack_h(v10, v11);
                }
            }
        }
    }
}

// ======================= flash attention v8: v6 + hoisted Q fragments ===========
#define ROWB 144
#define TILEB 18432
#define AB_Q  0
#define AB_K  (2*TILEB)
#define AB_V  (4*TILEB)
#define AB_ST (6*TILEB)
#define ATTN_SMEM_BYTES (6*TILEB + 1024)

__global__ __launch_bounds__(256, 1)
void attn_mma8_kernel(const __half* __restrict__ qhi, const __half* __restrict__ qlo,
                      const __half* __restrict__ kk, const __half* __restrict__ vv,
                      __half* __restrict__ ohi, __half* __restrict__ olo)
{
    extern __shared__ uint32_t su[];
    const uint32_t sbase = smem_u32(su);
    float2* stats = (float2*)(su + AB_ST / 4);

    const int tid  = threadIdx.x;
    const int wid  = tid >> 5;
    const int lid  = tid & 31;
    const int wg   = wid & 3;
    const int half = wid >> 2;
    const int r    = lid >> 2;
    const int c4   = lid & 3;
    const int i8   = lid & 7;
    const int m8   = lid >> 3;
    const int bh   = blockIdx.y;
    const int qt   = gridDim.x - 1 - blockIdx.x;
    const int q0   = qt * 128;

    const __half* qhp = qhi + (size_t)bh * SS * DK;
    const __half* qlp = qlo + (size_t)bh * SS * DK;
    const __half* khp = kk  + (size_t)bh * SS * DK;
    const __half* vhp = vv  + (size_t)bh * SS * DK;

    auto tile_cp = [&](uint32_t dstB, const __half* src, int row0g) {
        #pragma unroll
        for (int t = 0; t < 4; t++) {
            int id = tid + t * 256;
            int row = id >> 3, ch = id & 7;
            cp16(dstB + row * ROWB + ch * 16, src + (size_t)(row0g + row) * DK + ch * 8);
        }
    };
    auto prefetch_kv = [&](int kt, int buf) {
        int k0 = kt * 128;
        tile_cp(sbase + AB_K + buf * TILEB, khp, k0);
        tile_cp(sbase + AB_V + buf * TILEB, vhp, k0);
        CP_COMMIT();
    };

    // Q group (own commit), then KV tile 0 group
    tile_cp(sbase + AB_Q,         qhp, q0);
    tile_cp(sbase + AB_Q + TILEB, qlp, q0);
    CP_COMMIT();
    prefetch_kv(0, 0);

    const uint32_t qa_lane = sbase + AB_Q +
        (uint32_t)(wg * 32 + i8 + ((m8 & 1) << 3)) * ROWB + ((m8 & 2) << 3);
    const uint32_t kb_lane = (uint32_t)(half * 64 + i8 + ((m8 & 2) << 2)) * ROWB + ((m8 & 1) << 4);
    const uint32_t va_lane = (uint32_t)(half * 64 + i8 + ((m8 & 1) << 3)) * ROWB + ((m8 & 2) << 3);

    // wait for Q group only (KV tile 0 may still be in flight), then hoist Q frags
    CP_WAIT1();
    __syncthreads();
    uint32_t qfh[2][4][4], qfl[2][4][4];   // [mb][kc][reg], loop-invariant
    #pragma unroll
    for (int kc = 0; kc < 4; kc++) {
        LDSM4(qfh[0][kc], qa_lane + kc * 32);
        LDSM4(qfl[0][kc], qa_lane + TILEB + kc * 32);
        LDSM4(qfh[1][kc], qa_lane + 16 * ROWB + kc * 32);
        LDSM4(qfl[1][kc], qa_lane + TILEB + 16 * ROWB + kc * 32);
    }

    float mrow[4], lrow[4];
    float O[2][8][4];
    #pragma unroll
    for (int i = 0; i < 4; i++) { mrow[i] = -CUDART_INF_F; lrow[i] = 0.f; }
    #pragma unroll
    for (int mb = 0; mb < 2; mb++)
        #pragma unroll
        for (int a = 0; a < 8; a++)
            #pragma unroll
            for (int b2 = 0; b2 < 4; b2++) O[mb][a][b2] = 0.f;

    for (int kt = 0; kt <= qt; kt++) {
        CP_WAIT0();
        __syncthreads();
        if (kt < qt) prefetch_kv(kt + 1, (kt + 1) & 1);

        const uint32_t kbuf = sbase + AB_K + (kt & 1) * TILEB;
        const uint32_t vbuf = sbase + AB_V + (kt & 1) * TILEB;

        float Sv[2][8][4];
        #pragma unroll
        for (int mb = 0; mb < 2; mb++)
            #pragma unroll
            for (int nt = 0; nt < 8; nt++)
                #pragma unroll
                for (int q = 0; q < 4; q++) Sv[mb][nt][q] = 0.f;

        #pragma unroll
        for (int kc = 0; kc < 4; kc++) {
            #pragma unroll
            for (int ntp = 0; ntp < 4; ntp++) {
                uint32_t bhv[4];
                LDSM4(bhv, kbuf + kb_lane + ntp * (16 * ROWB) + kc * 32);
                #pragma unroll
                for (int mb = 0; mb < 2; mb++) {
                    mma_f16(Sv[mb][2*ntp],   qfh[mb][kc], bhv[0], bhv[1]);
                    mma_f16(Sv[mb][2*ntp+1], qfh[mb][kc], bhv[2], bhv[3]);
                    mma_f16(Sv[mb][2*ntp],   qfl[mb][kc], bhv[0], bhv[1]);
                    mma_f16(Sv[mb][2*ntp+1], qfl[mb][kc], bhv[2], bhv[3]);
                }
            }
        }

        if (kt == qt) {
            #pragma unroll
            for (int mb = 0; mb < 2; mb++) {
                int row0 = wg * 32 + mb * 16 + r;
                #pragma unroll
                for (int nt = 0; nt < 8; nt++) {
                    int col = half * 64 + nt * 8 + c4 * 2;
                    if (col     > row0)     Sv[mb][nt][0] = -1e30f;
                    if (col + 1 > row0)     Sv[mb][nt][1] = -1e30f;
                    if (col     > row0 + 8) Sv[mb][nt][2] = -1e30f;
                    if (col + 1 > row0 + 8) Sv[mb][nt][3] = -1e30f;
                }
            }
        }

        #pragma unroll
        for (int mb = 0; mb < 2; mb++) {
            #pragma unroll
            for (int hrow = 0; hrow < 2; hrow++) {
                const int ix = mb * 2 + hrow;
                float tm = -1e30f;
                #pragma unroll
                for (int nt = 0; nt < 8; nt++) {
                    tm = fmaxf(tm, Sv[mb][nt][2*hrow]);
                    tm = fmaxf(tm, Sv[mb][nt][2*hrow + 1]);
                }
                tm = fmaxf(tm, __shfl_xor_sync(0xffffffffu, tm, 1));
                tm = fmaxf(tm, __shfl_xor_sync(0xffffffffu, tm, 2));
                float mn = fmaxf(mrow[ix], tm);
                float alpha = exp2a(mrow[ix] - mn);
                float s = 0.f;
                #pragma unroll
                for (int nt = 0; nt < 8; nt++) {
                    float e0 = exp2a(Sv[mb][nt][2*hrow]     - mn);
                    float e1 = exp2a(Sv[mb][nt][2*hrow + 1] - mn);
                    Sv[mb][nt][2*hrow]     = e0;
                    Sv[mb][nt][2*hrow + 1] = e1;
                    s += e0 + e1;
                }
                s += __shfl_xor_sync(0xffffffffu, s, 1);
                s += __shfl_xor_sync(0xffffffffu, s, 2);
                lrow[ix] = lrow[ix] * alpha + s;
                mrow[ix] = mn;
                #pragma unroll
                for (int nt2 = 0; nt2 < 8; nt2++) {
                    O[mb][nt2][2*hrow]     *= alpha;
                    O[mb][nt2][2*hrow + 1] *= alpha;
                }
            }
        }

        #pragma unroll
        for (int kc2 = 0; kc2 < 4; kc2++) {
            uint32_t pah[2][4], pal[2][4];
            #pragma unroll
            for (int mb = 0; mb < 2; mb++) {
                split_pack_h(Sv[mb][2*kc2][0],   Sv[mb][2*kc2][1],   pah[mb][0], pal[mb][0]);
                split_pack_h(Sv[mb][2*kc2][2],   Sv[mb][2*kc2][3],   pah[mb][1], pal[mb][1]);
                split_pack_h(Sv[mb][2*kc2+1][0], Sv[mb][2*kc2+1][1], pah[mb][2], pal[mb][2]);
                split_pack_h(Sv[mb][2*kc2+1][2], Sv[mb][2*kc2+1][3], pah[mb][3], pal[mb][3]);
            }
            uint32_t va0 = vbuf + va_lane + kc2 * (16 * ROWB);
            #pragma unroll
            for (int g = 0; g < 4; g++) {
                uint32_t bhv[4];
                LDSM4T(bhv, va0 + g * 32);
                #pragma unroll
                for (int mb = 0; mb < 2; mb++) {
                    mma_f16(O[mb][2*g],   pah[mb], bhv[0], bhv[1]);
                    mma_f16(O[mb][2*g+1], pah[mb], bhv[2], bhv[3]);
                    mma_f16(O[mb][2*g],   pal[mb], bhv[0], bhv[1]);
                    mma_f16(O[mb][2*g+1], pal[mb], bhv[2], bhv[3]);
                }
            }
        }
    }

    __syncthreads();
    float* osm = (float*)su;
    if (half == 1) {
        #pragma unroll
        for (int mb = 0; mb < 2; mb++) {
            int srow = wg * 32 + mb * 16 + r;
            #pragma unroll
            for (int nt2 = 0; nt2 < 8; nt2++) {
                int col = nt2 * 8 + c4 * 2;
                *(float2*)&osm[(srow)     * 66 + col] = make_float2(O[mb][nt2][0], O[mb][nt2][1]);
                *(float2*)&osm[(srow + 8) * 66 + col] = make_float2(O[mb][nt2][2], O[mb][nt2][3]);
            }
            if (c4 == 0) {
                stats[srow]     = make_float2(mrow[mb*2],     lrow[mb*2]);
                stats[srow + 8] = make_float2(mrow[mb*2 + 1], lrow[mb*2 + 1]);
            }
        }
    }
    __syncthreads();
    if (half == 0) {
        const int b = bh >> 4, h = bh & 15;
        #pragma unroll
        for (int mb = 0; mb < 2; mb++) {
            int srow = wg * 32 + mb * 16 + r;
            float2 st0 = stats[srow];
            float2 st1 = stats[srow + 8];
            float nm0 = fmaxf(mrow[mb*2],     st0.x);
            float nm1 = fmaxf(mrow[mb*2 + 1], st1.x);
            float e00 = exp2a(mrow[mb*2]     - nm0), e01 = exp2a(st0.x - nm0);
            float e10 = exp2a(mrow[mb*2 + 1] - nm1), e11 = exp2a(st1.x - nm1);
            float inv0 = 1.0f / (lrow[mb*2]     * e00 + st0.y * e01);
            float inv1 = 1.0f / (lrow[mb*2 + 1] * e10 + st1.y * e11);
            const int row0g = q0 + srow;
            const int row1g = row0g + 8;
            #pragma unroll
            for (int nt2 = 0; nt2 < 8; nt2++) {
                int col = nt2 * 8 + c4 * 2;
                float2 p0 = *(float2*)&osm[(srow)     * 66 + col];
                float2 p1 = *(float2*)&osm[(srow + 8) * 66 + col];
                float v00 = (O[mb][nt2][0] * e00 + p0.x * e01) * inv0;
                float v01 = (O[mb][nt2][1] * e00 + p0.y * e01) * inv0;
                float v10 = (O[mb][nt2][2] * e10 + p1.x * e11) * inv1;
                float v11 = (O[mb][nt2][3] * e10 + p1.y * e11) * inv1;
                uint32_t h0, l0, h1, l1;
                split_pack_h(v00, v01, h0, l0);
                split_pack_h(v10, v11, h1, l1);
                int gcol = h * DK + col;
                size_t o0 = ((size_t)(b * SS + row0g) * DD + gcol) >> 1;
                size_t o1 = ((size_t)(b * SS + row1g) * DD + gcol) >> 1;
                ((uint32_t*)ohi)[o0] = h0;
                ((uint32_t*)olo)[o0] = l0;
                ((uint32_t*)ohi)[o1] = h1;
                ((uint32_t*)olo)[o1] = l1;
            }
        }
    }
}

// ---------------- launch --------------------------------------------------------
extern "C" void kernel_launch(void* const* d_in, const int* in_sizes, int n_in,
                              void* d_out, int out_size)
{
    (void)in_sizes; (void)n_in; (void)out_size;
    const float* x  = (const float*)d_in[0];
    const float* Wq = (const float*)d_in[1];
    const float* Wk = (const float*)d_in[2];
    const float* Wv = (const float*)d_in[3];
    const float* Wo = (const float*)d_in[4];
    const int*   tp = (const int*)d_in[5];
    float* out = (float*)d_out;

    float *ct, *st;
    __half *xhi, *xlo, *wc, *wo, *qhi, *qlo, *kk, *vv, *abhi, *ablo;
    cudaGetSymbolAddress((void**)&ct, g_ct);
    cudaGetSymbolAddress((void**)&st, g_st);
    cudaGetSymbolAddress((void**)&xhi, g_xhi);   cudaGetSymbolAddress((void**)&xlo, g_xlo);
    cudaGetSymbolAddress((void**)&wc, g_wc);     cudaGetSymbolAddress((void**)&wo, g_wo);
    cudaGetSymbolAddress((void**)&qhi, g_qhi);   cudaGetSymbolAddress((void**)&qlo, g_qlo);
    cudaGetSymbolAddress((void**)&kk, g_kk);     cudaGetSymbolAddress((void**)&vv, g_vv);
    cudaGetSymbolAddress((void**)&abhi, g_abhi); cudaGetSymbolAddress((void**)&ablo, g_ablo);

    cudaFuncSetAttribute(gemm_mma6_kernel, cudaFuncAttributeMaxDynamicSharedMemorySize,
                         G5_SMEM_BYTES);
    cudaFuncSetAttribute(attn_mma8_kernel, cudaFuncAttributeMaxDynamicSharedMemorySize,
                         ATTN_SMEM_BYTES);

    const int ntot = NX4 + 4 * NW4;
    cvt_all_kernel<<<(ntot + 255)/256, 256>>>(x, Wq, Wk, Wv, Wo, xhi, xlo, wc, wo);
    rope_tab_kernel<<<(BB*SS*32 + 255)/256, 256>>>(tp, ct, st);

    gemm_mma6_kernel<<<dim3(24, (BB*SS)/128), 128, G5_SMEM_BYTES>>>(
        xhi, xlo, wc, ct, st, qhi, qlo, kk, vv, nullptr, 3);

    attn_mma8_kernel<<<dim3(SS / 128, BB * HH), 256, ATTN_SMEM_BYTES>>>(
        qhi, qlo, kk, vv, abhi, ablo);

    gemm_mma6_kernel<<<dim3(8, (BB*SS)/128), 128, G5_SMEM_BYTES>>>(
        abhi, ablo, wo, ct, st, nullptr, nullptr, nullptr, nullptr, out, 2);
}

// round 15
// speedup vs baseline: 1.0820x; 1.0820x over previous
#include <cuda_runtime.h>
#include <cuda_bf16.h>
#include <cuda_fp16.h>
#include <math.h>
#include <math_constants.h>
#include <cstdint>

#define BB 2
#define SS 2048
#define DD 1024
#define HH 16
#define DK 64

// ---------------- scratch (allocation-free: __device__ globals) ----------------
__device__ float g_ct[BB*SS*32];
__device__ float g_st[BB*SS*32];
__device__ __half g_xhi[BB*SS*DD], g_xlo[BB*SS*DD];
__device__ __half g_wc[3*DD*DD];                    // Wq|Wk|Wv single fp16
__device__ __half g_wo[DD*DD];                      // Wo single fp16
__device__ __half g_qhi[BB*HH*SS*DK], g_qlo[BB*HH*SS*DK];  // headed, rope'd, *CSC
__device__ __half g_kk[BB*HH*SS*DK];                // headed, rope'd, single
__device__ __half g_vv[BB*HH*SS*DK];                // headed, single
__device__ __half g_abhi[BB*SS*DD], g_ablo[BB*SS*DD];

// ======================= helpers ================================================
__device__ __forceinline__ uint32_t smem_u32(const void* p) {
    uint32_t a;
    asm("{ .reg .u64 t; cvta.to.shared.u64 t, %1; cvt.u32.u64 %0, t; }" : "=r"(a) : "l"(p));
    return a;
}
__device__ __forceinline__ uint32_t pack_h(float a, float b) {
    __half2 h = __floats2half2_rn(a, b);
    return *(uint32_t*)&h;
}
__device__ __forceinline__ void split_pack_h(float a, float b, uint32_t& hi, uint32_t& lo) {
    __half ha = __float2half_rn(a);
    __half hb = __float2half_rn(b);
    hi = (uint32_t)__half_as_ushort(ha) | ((uint32_t)__half_as_ushort(hb) << 16);
    lo = pack_h(a - __half2float(ha), b - __half2float(hb));
}
__device__ __forceinline__ void mma_f16(float c[4], const uint32_t a[4],
                                        uint32_t b0, uint32_t b1) {
    asm volatile(
        "mma.sync.aligned.m16n8k16.row.col.f32.f16.f16.f32 "
        "{%0,%1,%2,%3},{%4,%5,%6,%7},{%8,%9},{%0,%1,%2,%3};"
        : "+f"(c[0]), "+f"(c[1]), "+f"(c[2]), "+f"(c[3])
        : "r"(a[0]), "r"(a[1]), "r"(a[2]), "r"(a[3]), "r"(b0), "r"(b1));
}
__device__ __forceinline__ float exp2a(float x) {
    x = fmaxf(x, -126.0f);
    float z = x + 12582912.0f;
    uint32_t iz = __float_as_uint(z);
    float f = x - (z - 12582912.0f);
    float p = 0.0013333558f;
    p = fmaf(p, f, 0.0096180885f);
    p = fmaf(p, f, 0.0555041087f);
    p = fmaf(p, f, 0.2402265069f);
    p = fmaf(p, f, 0.6931471806f);
    p = fmaf(p, f, 1.0f);
    return __uint_as_float(__float_as_uint(p) + (iz << 23));
}
__device__ __forceinline__ void cp16(uint32_t dst, const void* src) {
    asm volatile("cp.async.ca.shared.global [%0], [%1], 16;" :: "r"(dst), "l"(src));
}
#define CP_COMMIT() asm volatile("cp.async.commit_group;" ::: "memory")
#define CP_WAIT0()  asm volatile("cp.async.wait_group 0;" ::: "memory")
#define LDSM4(d, a) \
    asm volatile("ldmatrix.sync.aligned.m8n8.x4.shared.b16 {%0,%1,%2,%3},[%4];" \
        : "=r"((d)[0]), "=r"((d)[1]), "=r"((d)[2]), "=r"((d)[3]) : "r"(a))
#define LDSM4T(d, a) \
    asm volatile("ldmatrix.sync.aligned.m8n8.x4.trans.shared.b16 {%0,%1,%2,%3},[%4];" \
        : "=r"((d)[0]), "=r"((d)[1]), "=r"((d)[2]), "=r"((d)[3]) : "r"(a))

// ======================= pre-pass conversions ===================================
#define NX4 (BB*SS*DD/4)
#define NW4 (DD*DD/4)
__global__ void cvt_all_kernel(const float* __restrict__ x,  const float* __restrict__ Wq,
                               const float* __restrict__ Wk, const float* __restrict__ Wv,
                               const float* __restrict__ Wo,
                               __half* __restrict__ xhi, __half* __restrict__ xlo,
                               __half* __restrict__ wc, __half* __restrict__ wo)
{
    int idx = blockIdx.x * blockDim.x + threadIdx.x;
    if (idx < NX4) {
        float4 v = *(const float4*)&x[(size_t)idx * 4];
        uint32_t h0, l0, h1, l1;
        split_pack_h(v.x, v.y, h0, l0);
        split_pack_h(v.z, v.w, h1, l1);
        *(uint2*)&xhi[(size_t)idx * 4] = make_uint2(h0, h1);
        *(uint2*)&xlo[(size_t)idx * 4] = make_uint2(l0, l1);
        return;
    }
    const float* src;
    __half* dst;
    int off;
    if (idx < NX4 + NW4)        { src = Wq; dst = wc;             off = idx - NX4; }
    else if (idx < NX4 + 2*NW4) { src = Wk; dst = wc + DD*DD;     off = idx - NX4 - NW4; }
    else if (idx < NX4 + 3*NW4) { src = Wv; dst = wc + 2*DD*DD;   off = idx - NX4 - 2*NW4; }
    else if (idx < NX4 + 4*NW4) { src = Wo; dst = wo;             off = idx - NX4 - 3*NW4; }
    else return;
    float4 v = *(const float4*)&src[(size_t)off * 4];
    *(uint2*)&dst[(size_t)off * 4] = make_uint2(pack_h(v.x, v.y), pack_h(v.z, v.w));
}

// ======================= RoPE table =============================================
__global__ void rope_tab_kernel(const int* __restrict__ tp, float* __restrict__ ct,
                                float* __restrict__ st)
{
    int idx = blockIdx.x * blockDim.x + threadIdx.x;
    if (idx >= BB*SS*32) return;
    int m = idx >> 5;
    int p = idx & 31;
    float inv = powf(10000.0f, -(float)(2*p) * (1.0f/64.0f));
    float freq = (float)tp[m] * inv;
    float sn, cs;
    sincosf(freq, &sn, &cs);
    ct[idx] = cs;
    st[idx] = sn;
}

// ======================= GEMM v8: 1-pass for K/V segs, 2-pass for Q/Wo ==========
#define SROW 20
#define SROWB (SROW*4)
#define G5_ARR 2560
#define G5_STAGE (3*G5_ARR)
#define G5_SMEM_BYTES (2*G5_STAGE*4)   // 61440
#define CSCALE (0.125f * 1.44269504088896f)

__global__ __launch_bounds__(128, 2)
void gemm_mma8_kernel(const __half* __restrict__ Ahi, const __half* __restrict__ Alo,
                      const __half* __restrict__ Bh,
                      const float* __restrict__ ct, const float* __restrict__ st,
                      __half* __restrict__ qhi, __half* __restrict__ qlo,
                      __half* __restrict__ kkp, __half* __restrict__ vvp,
                      float* __restrict__ outp, int mode)
{
    extern __shared__ uint32_t su2[];
    const uint32_t sbase = smem_u32(su2);

    const int tid = threadIdx.x;
    const int wid = tid >> 5;
    const int lid = tid & 31;
    const int wm = wid >> 1;
    const int wn = wid & 1;
    const int r  = lid >> 2;
    const int c4 = lid & 3;
    const int i8 = lid & 7;
    const int m8 = lid >> 3;
    const int m0 = blockIdx.y * 128;

    int n0, seg;
    const __half* bp = Bh;
    if (mode == 3) {
        seg = blockIdx.x >> 3;
        n0 = (blockIdx.x & 7) * 128;
        bp += (size_t)seg * DD * DD;
    } else {
        seg = 3;
        n0 = blockIdx.x * 128;
    }
    // K/V outputs are rounded to single fp16 downstream -> 1-pass suffices
    const bool twoPass = (seg == 0 || seg == 3);

    const int prow = tid >> 2;
    const int pch  = tid & 3;

    float C[4][8][4];
    #pragma unroll
    for (int mt = 0; mt < 4; mt++)
        #pragma unroll
        for (int nt = 0; nt < 8; nt++)
            #pragma unroll
            for (int q = 0; q < 4; q++) C[mt][nt][q] = 0.f;

    auto prefetch = [&](int kt, int st2) {
        const int k0 = kt * 32;
        #pragma unroll
        for (int i = 0; i < 4; i++) {
            int row = prow + i * 32;
            uint32_t d = sbase + (uint32_t)(st2 * G5_STAGE + row * SROW + pch * 4) * 4u;
            size_t goA = (size_t)(m0 + row) * DD + k0 + pch * 8;
            size_t goB = (size_t)(n0 + row) * DD + k0 + pch * 8;
            cp16(d,                Ahi + goA);
            if (twoPass) cp16(d + G5_ARR * 4u, Alo + goA);
            cp16(d + 2u*G5_ARR*4u, bp  + goB);
        }
        CP_COMMIT();
    };

    prefetch(0, 0);

    const uint32_t aLane = (uint32_t)(wm * 64 + i8 + ((m8 & 1) << 3)) * SROWB + ((m8 & 2) << 3);
    const uint32_t bLane = (uint32_t)(wn * 64 + i8 + ((m8 & 2) << 2)) * SROWB + ((m8 & 1) << 4);

    for (int kt = 0; kt < 32; kt++) {
        CP_WAIT0();
        __syncthreads();
        if (kt < 31) prefetch(kt + 1, (kt + 1) & 1);

        const uint32_t stageB = sbase + (uint32_t)((kt & 1) * G5_STAGE) * 4u;
        const uint32_t aHiB = stageB;
        const uint32_t aLoB = stageB + G5_ARR * 4u;
        const uint32_t bB   = stageB + 2u * G5_ARR * 4u;

        #pragma unroll
        for (int kc = 0; kc < 2; kc++) {
            uint32_t bh[4][4];
            #pragma unroll
            for (int p = 0; p < 4; p++)
                LDSM4(bh[p], bB + bLane + p * (16 * SROWB) + kc * 32);
            #pragma unroll
            for (int mt = 0; mt < 4; mt++) {
                uint32_t ah[4];
                LDSM4(ah, aHiB + aLane + mt * (16 * SROWB) + kc * 32);
                #pragma unroll
                for (int p = 0; p < 4; p++) {
                    mma_f16(C[mt][2*p],   ah, bh[p][0], bh[p][1]);
                    mma_f16(C[mt][2*p+1], ah, bh[p][2], bh[p][3]);
                }
                if (twoPass) {
                    uint32_t al[4];
                    LDSM4(al, aLoB + aLane + mt * (16 * SROWB) + kc * 32);
                    #pragma unroll
                    for (int p = 0; p < 4; p++) {
                        mma_f16(C[mt][2*p],   al, bh[p][0], bh[p][1]);
                        mma_f16(C[mt][2*p+1], al, bh[p][2], bh[p][3]);
                    }
                }
            }
        }
    }

    #pragma unroll
    for (int mt = 0; mt < 4; mt++) {
        const int row0 = m0 + wm * 64 + mt * 16 + r;
        const int row1 = row0 + 8;
        #pragma unroll
        for (int nt = 0; nt < 8; nt++) {
            const int ncol = n0 + wn * 64 + nt * 8 + c4 * 2;
            float v00 = C[mt][nt][0], v01 = C[mt][nt][1];
            float v10 = C[mt][nt][2], v11 = C[mt][nt][3];
            if (seg == 3) {
                *(float2*)&outp[(size_t)row0 * DD + ncol] = make_float2(v00, v01);
                *(float2*)&outp[(size_t)row1 * DD + ncol] = make_float2(v10, v11);
            } else {
                const int h   = ncol >> 6;
                const int dk0 = ncol & 63;
                if (seg < 2) {
                    const int p = dk0 >> 1;
                    float cs0 = ct[(size_t)row0 * 32 + p], sn0 = st[(size_t)row0 * 32 + p];
                    float cs1 = ct[(size_t)row1 * 32 + p], sn1 = st[(size_t)row1 * 32 + p];
                    float t00 = cs0 * v00 - sn0 * v01;
                    float t01 = sn0 * v00 + cs0 * v01;
                    float t10 = cs1 * v10 - sn1 * v11;
                    float t11 = sn1 * v10 + cs1 * v11;
                    v00 = t00; v01 = t01; v10 = t10; v11 = t11;
                    if (seg == 0) { v00 *= CSCALE; v01 *= CSCALE; v10 *= CSCALE; v11 *= CSCALE; }
                }
                const int b0r = row0 >> 11, s0 = row0 & (SS - 1);
                const int b1r = row1 >> 11, s1 = row1 & (SS - 1);
                size_t hb0 = ((size_t)(b0r * HH + h) * SS + s0) * 32 + (dk0 >> 1);
                size_t hb1 = ((size_t)(b1r * HH + h) * SS + s1) * 32 + (dk0 >> 1);
                if (seg == 0) {
                    uint32_t h0, l0, h1, l1;
                    split_pack_h(v00, v01, h0, l0);
                    split_pack_h(v10, v11, h1, l1);
                    ((uint32_t*)qhi)[hb0] = h0;  ((uint32_t*)qlo)[hb0] = l0;
                    ((uint32_t*)qhi)[hb1] = h1;  ((uint32_t*)qlo)[hb1] = l1;
                } else if (seg == 1) {
                    ((uint32_t*)kkp)[hb0] = pack_h(v00, v01);
                    ((uint32_t*)kkp)[hb1] = pack_h(v10, v11);
                } else {
                    ((uint32_t*)vvp)[hb0] = pack_h(v00, v01);
                    ((uint32_t*)vvp)[hb1] = pack_h(v10, v11);
                }
            }
        }
    }
}

// ======================= flash attention v6 (round-12, unchanged) ===============
#define ROWB 144
#define TILEB 18432
#define AB_Q  0
#define AB_K  (2*TILEB)
#define AB_V  (4*TILEB)
#define AB_ST (6*TILEB)
#define ATTN_SMEM_BYTES (6*TILEB + 1024)

__global__ __launch_bounds__(256)
void attn_mma6_kernel(const __half* __restrict__ qhi, const __half* __restrict__ qlo,
                      const __half* __restrict__ kk, const __half* __restrict__ vv,
                      __half* __restrict__ ohi, __half* __restrict__ olo)
{
    extern __shared__ uint32_t su[];
    const uint32_t sbase = smem_u32(su);
    float2* stats = (float2*)(su + AB_ST / 4);

    const int tid  = threadIdx.x;
    const int wid  = tid >> 5;
    const int lid  = tid & 31;
    const int wg   = wid & 3;
    const int half = wid >> 2;
    const int r    = lid >> 2;
    const int c4   = lid & 3;
    const int i8   = lid & 7;
    const int m8   = lid >> 3;
    const int bh   = blockIdx.y;
    const int qt   = gridDim.x - 1 - blockIdx.x;
    const int q0   = qt * 128;

    const __half* qhp = qhi + (size_t)bh * SS * DK;
    const __half* qlp = qlo + (size_t)bh * SS * DK;
    const __half* khp = kk  + (size_t)bh * SS * DK;
    const __half* vhp = vv  + (size_t)bh * SS * DK;

    auto tile_cp = [&](uint32_t dstB, const __half* src, int row0g) {
        #pragma unroll
        for (int t = 0; t < 4; t++) {
            int id = tid + t * 256;
            int row = id >> 3, ch = id & 7;
            cp16(dstB + row * ROWB + ch * 16, src + (size_t)(row0g + row) * DK + ch * 8);
        }
    };
    auto prefetch_kv = [&](int kt, int buf) {
        int k0 = kt * 128;
        tile_cp(sbase + AB_K + buf * TILEB, khp, k0);
        tile_cp(sbase + AB_V + buf * TILEB, vhp, k0);
        CP_COMMIT();
    };

    tile_cp(sbase + AB_Q,         qhp, q0);
    tile_cp(sbase + AB_Q + TILEB, qlp, q0);
    prefetch_kv(0, 0);

    float mrow[4], lrow[4];
    float O[2][8][4];
    #pragma unroll
    for (int i = 0; i < 4; i++) { mrow[i] = -CUDART_INF_F; lrow[i] = 0.f; }
    #pragma unroll
    for (int mb = 0; mb < 2; mb++)
        #pragma unroll
        for (int a = 0; a < 8; a++)
            #pragma unroll
            for (int b2 = 0; b2 < 4; b2++) O[mb][a][b2] = 0.f;

    const uint32_t qa_lane = sbase + AB_Q +
        (uint32_t)(wg * 32 + i8 + ((m8 & 1) << 3)) * ROWB + ((m8 & 2) << 3);
    const uint32_t kb_lane = (uint32_t)(half * 64 + i8 + ((m8 & 2) << 2)) * ROWB + ((m8 & 1) << 4);
    const uint32_t va_lane = (uint32_t)(half * 64 + i8 + ((m8 & 1) << 3)) * ROWB + ((m8 & 2) << 3);

    for (int kt = 0; kt <= qt; kt++) {
        CP_WAIT0();
        __syncthreads();
        if (kt < qt) prefetch_kv(kt + 1, (kt + 1) & 1);

        const uint32_t kbuf = sbase + AB_K + (kt & 1) * TILEB;
        const uint32_t vbuf = sbase + AB_V + (kt & 1) * TILEB;

        float Sv[2][8][4];
        #pragma unroll
        for (int mb = 0; mb < 2; mb++)
            #pragma unroll
            for (int nt = 0; nt < 8; nt++)
                #pragma unroll
                for (int q = 0; q < 4; q++) Sv[mb][nt][q] = 0.f;

        #pragma unroll
        for (int kc = 0; kc < 4; kc++) {
            uint32_t ah[2][4], al[2][4];
            LDSM4(ah[0], qa_lane + kc * 32);
            LDSM4(al[0], qa_lane + TILEB + kc * 32);
            LDSM4(ah[1], qa_lane + 16 * ROWB + kc * 32);
            LDSM4(al[1], qa_lane + TILEB + 16 * ROWB + kc * 32);
            #pragma unroll
            for (int ntp = 0; ntp < 4; ntp++) {
                uint32_t bhv[4];
                LDSM4(bhv, kbuf + kb_lane + ntp * (16 * ROWB) + kc * 32);
                #pragma unroll
                for (int mb = 0; mb < 2; mb++) {
                    mma_f16(Sv[mb][2*ntp],   ah[mb], bhv[0], bhv[1]);
                    mma_f16(Sv[mb][2*ntp+1], ah[mb], bhv[2], bhv[3]);
                    mma_f16(Sv[mb][2*ntp],   al[mb], bhv[0], bhv[1]);
                    mma_f16(Sv[mb][2*ntp+1], al[mb], bhv[2], bhv[3]);
                }
            }
        }

        if (kt == qt) {
            #pragma unroll
            for (int mb = 0; mb < 2; mb++) {
                int row0 = wg * 32 + mb * 16 + r;
                #pragma unroll
                for (int nt = 0; nt < 8; nt++) {
                    int col = half * 64 + nt * 8 + c4 * 2;
                    if (col     > row0)     Sv[mb][nt][0] = -1e30f;
                    if (col + 1 > row0)     Sv[mb][nt][1] = -1e30f;
                    if (col     > row0 + 8) Sv[mb][nt][2] = -1e30f;
                    if (col + 1 > row0 + 8) Sv[mb][nt][3] = -1e30f;
                }
            }
        }

        #pragma unroll
        for (int mb = 0; mb < 2; mb++) {
            #pragma unroll
            for (int hrow = 0; hrow < 2; hrow++) {
                const int ix = mb * 2 + hrow;
                float tm = -1e30f;
                #pragma unroll
                for (int nt = 0; nt < 8; nt++) {
                    tm = fmaxf(tm, Sv[mb][nt][2*hrow]);
                    tm = fmaxf(tm, Sv[mb][nt][2*hrow + 1]);
                }
                tm = fmaxf(tm, __shfl_xor_sync(0xffffffffu, tm, 1));
                tm = fmaxf(tm, __shfl_xor_sync(0xffffffffu, tm, 2));
                float mn = fmaxf(mrow[ix], tm);
                float alpha = exp2a(mrow[ix] - mn);
                float s = 0.f;
                #pragma unroll
                for (int nt = 0; nt < 8; nt++) {
                    float e0 = exp2a(Sv[mb][nt][2*hrow]     - mn);
                    float e1 = exp2a(Sv[mb][nt][2*hrow + 1] - mn);
                    Sv[mb][nt][2*hrow]     = e0;
                    Sv[mb][nt][2*hrow + 1] = e1;
                    s += e0 + e1;
                }
                s += __shfl_xor_sync(0xffffffffu, s, 1);
                s += __shfl_xor_sync(0xffffffffu, s, 2);
                lrow[ix] = lrow[ix] * alpha + s;
                mrow[ix] = mn;
                #pragma unroll
                for (int nt2 = 0; nt2 < 8; nt2++) {
                    O[mb][nt2][2*hrow]     *= alpha;
                    O[mb][nt2][2*hrow + 1] *= alpha;
                }
            }
        }

        #pragma unroll
        for (int kc2 = 0; kc2 < 4; kc2++) {
            uint32_t pah[2][4], pal[2][4];
            #pragma unroll
            for (int mb = 0; mb < 2; mb++) {
                split_pack_h(Sv[mb][2*kc2][0],   Sv[mb][2*kc2][1],   pah[mb][0], pal[mb][0]);
                split_pack_h(Sv[mb][2*kc2][2],   Sv[mb][2*kc2][3],   pah[mb][1], pal[mb][1]);
                split_pack_h(Sv[mb][2*kc2+1][0], Sv[mb][2*kc2+1][1], pah[mb][2], pal[mb][2]);
                split_pack_h(Sv[mb][2*kc2+1][2], Sv[mb][2*kc2+1][3], pah[mb][3], pal[mb][3]);
            }
            uint32_t va0 = vbuf + va_lane + kc2 * (16 * ROWB);
            #pragma unroll
            for (int g = 0; g < 4; g++) {
                uint32_t bhv[4];
                LDSM4T(bhv, va0 + g * 32);
                #pragma unroll
                for (int mb = 0; mb < 2; mb++) {
                    mma_f16(O[mb][2*g],   pah[mb], bhv[0], bhv[1]);
                    mma_f16(O[mb][2*g+1], pah[mb], bhv[2], bhv[3]);
                    mma_f16(O[mb][2*g],   pal[mb], bhv[0], bhv[1]);
                    mma_f16(O[mb][2*g+1], pal[mb], bhv[2], bhv[3]);
                }
            }
        }
    }

    __syncthreads();
    float* osm = (float*)su;
    if (half == 1) {
        #pragma unroll
        for (int mb = 0; mb < 2; mb++) {
            int srow = wg * 32 + mb * 16 + r;
            #pragma unroll
            for (int nt2 = 0; nt2 < 8; nt2++) {
                int col = nt2 * 8 + c4 * 2;
                *(float2*)&osm[(srow)     * 66 + col] = make_float2(O[mb][nt2][0], O[mb][nt2][1]);
                *(float2*)&osm[(srow + 8) * 66 + col] = make_float2(O[mb][nt2][2], O[mb][nt2][3]);
            }
            if (c4 == 0) {
                stats[srow]     = make_float2(mrow[mb*2],     lrow[mb*2]);
                stats[srow + 8] = make_float2(mrow[mb*2 + 1], lrow[mb*2 + 1]);
            }
        }
    }
    __syncthreads();
    if (half == 0) {
        const int b = bh >> 4, h = bh & 15;
        #pragma unroll
        for (int mb = 0; mb < 2; mb++) {
            int srow = wg * 32 + mb * 16 + r;
            float2 st0 = stats[srow];
            float2 st1 = stats[srow + 8];
            float nm0 = fmaxf(mrow[mb*2],     st0.x);
            float nm1 = fmaxf(mrow[mb*2 + 1], st1.x);
            float e00 = exp2a(mrow[mb*2]     - nm0), e01 = exp2a(st0.x - nm0);
            float e10 = exp2a(mrow[mb*2 + 1] - nm1), e11 = exp2a(st1.x - nm1);
            float inv0 = 1.0f / (lrow[mb*2]     * e00 + st0.y * e01);
            float inv1 = 1.0f / (lrow[mb*2 + 1] * e10 + st1.y * e11);
            const int row0g = q0 + srow;
            const int row1g = row0g + 8;
            #pragma unroll
            for (int nt2 = 0; nt2 < 8; nt2++) {
                int col = nt2 * 8 + c4 * 2;
                float2 p0 = *(float2*)&osm[(srow)     * 66 + col];
                float2 p1 = *(float2*)&osm[(srow + 8) * 66 + col];
                float v00 = (O[mb][nt2][0] * e00 + p0.x * e01) * inv0;
                float v01 = (O[mb][nt2][1] * e00 + p0.y * e01) * inv0;
                float v10 = (O[mb][nt2][2] * e10 + p1.x * e11) * inv1;
                float v11 = (O[mb][nt2][3] * e10 + p1.y * e11) * inv1;
                uint32_t h0, l0, h1, l1;
                split_pack_h(v00, v01, h0, l0);
                split_pack_h(v10, v11, h1, l1);
                int gcol = h * DK + col;
                size_t o0 = ((size_t)(b * SS + row0g) * DD + gcol) >> 1;
                size_t o1 = ((size_t)(b * SS + row1g) * DD + gcol) >> 1;
                ((uint32_t*)ohi)[o0] = h0;
                ((uint32_t*)olo)[o0] = l0;
                ((uint32_t*)ohi)[o1] = h1;
                ((uint32_t*)olo)[o1] = l1;
            }
        }
    }
}

// ---------------- launch --------------------------------------------------------
extern "C" void kernel_launch(void* const* d_in, const int* in_sizes, int n_in,
                              void* d_out, int out_size)
{
    (void)in_sizes; (void)n_in; (void)out_size;
    const float* x  = (const float*)d_in[0];
    const float* Wq = (const float*)d_in[1];
    const float* Wk = (const float*)d_in[2];
    const float* Wv = (const float*)d_in[3];
    const float* Wo = (const float*)d_in[4];
    const int*   tp = (const int*)d_in[5];
    float* out = (float*)d_out;

    float *ct, *st;
    __half *xhi, *xlo, *wc, *wo, *qhi, *qlo, *kk, *vv, *abhi, *ablo;
    cudaGetSymbolAddress((void**)&ct, g_ct);
    cudaGetSymbolAddress((void**)&st, g_st);
    cudaGetSymbolAddress((void**)&xhi, g_xhi);   cudaGetSymbolAddress((void**)&xlo, g_xlo);
    cudaGetSymbolAddress((void**)&wc, g_wc);     cudaGetSymbolAddress((void**)&wo, g_wo);
    cudaGetSymbolAddress((void**)&qhi, g_qhi);   cudaGetSymbolAddress((void**)&qlo, g_qlo);
    cudaGetSymbolAddress((void**)&kk, g_kk);     cudaGetSymbolAddress((void**)&vv, g_vv);
    cudaGetSymbolAddress((void**)&abhi, g_abhi); cudaGetSymbolAddress((void**)&ablo, g_ablo);

    cudaFuncSetAttribute(gemm_mma8_kernel, cudaFuncAttributeMaxDynamicSharedMemorySize,
                         G5_SMEM_BYTES);
    cudaFuncSetAttribute(attn_mma6_kernel, cudaFuncAttributeMaxDynamicSharedMemorySize,
                         ATTN_SMEM_BYTES);

    const int ntot = NX4 + 4 * NW4;
    cvt_all_kernel<<<(ntot + 255)/256, 256>>>(x, Wq, Wk, Wv, Wo, xhi, xlo, wc, wo);
    rope_tab_kernel<<<(BB*SS*32 + 255)/256, 256>>>(tp, ct, st);

    gemm_mma8_kernel<<<dim3(24, (BB*SS)/128), 128, G5_SMEM_BYTES>>>(
        xhi, xlo, wc, ct, st, qhi, qlo, kk, vv, nullptr, 3);

    attn_mma6_kernel<<<dim3(SS / 128, BB * HH), 256, ATTN_SMEM_BYTES>>>(
        qhi, qlo, kk, vv, abhi, ablo);

    gemm_mma8_kernel<<<dim3(8, (BB*SS)/128), 128, G5_SMEM_BYTES>>>(
        abhi, ablo, wo, ct, st, nullptr, nullptr, nullptr, nullptr, out, 2);
}

// round 16
// speedup vs baseline: 1.1534x; 1.0660x over previous
#include <cuda_runtime.h>
#include <cuda_bf16.h>
#include <cuda_fp16.h>
#include <math.h>
#include <math_constants.h>
#include <cstdint>

#define BB 2
#define SS 2048
#define DD 1024
#define HH 16
#define DK 64

// ---------------- scratch (allocation-free: __device__ globals) ----------------
__device__ float g_ct[BB*SS*32];
__device__ float g_st[BB*SS*32];
__device__ __half g_xhi[BB*SS*DD], g_xlo[BB*SS*DD];
__device__ __half g_wc[3*DD*DD];                    // Wq|Wk|Wv single fp16
__device__ __half g_wo[DD*DD];                      // Wo single fp16
__device__ __half g_qhi[BB*HH*SS*DK], g_qlo[BB*HH*SS*DK];  // headed, rope'd, *CSC
__device__ __half g_kk[BB*HH*SS*DK];                // headed, rope'd, single
__device__ __half g_vv[BB*HH*SS*DK];                // headed, single
__device__ __half g_abhi[BB*SS*DD], g_ablo[BB*SS*DD];

// ======================= helpers ================================================
__device__ __forceinline__ uint32_t smem_u32(const void* p) {
    uint32_t a;
    asm("{ .reg .u64 t; cvta.to.shared.u64 t, %1; cvt.u32.u64 %0, t; }" : "=r"(a) : "l"(p));
    return a;
}
__device__ __forceinline__ uint32_t pack_h(float a, float b) {
    __half2 h = __floats2half2_rn(a, b);
    return *(uint32_t*)&h;
}
__device__ __forceinline__ void split_pack_h(float a, float b, uint32_t& hi, uint32_t& lo) {
    __half ha = __float2half_rn(a);
    __half hb = __float2half_rn(b);
    hi = (uint32_t)__half_as_ushort(ha) | ((uint32_t)__half_as_ushort(hb) << 16);
    lo = pack_h(a - __half2float(ha), b - __half2float(hb));
}
__device__ __forceinline__ void mma_f16(float c[4], const uint32_t a[4],
                                        uint32_t b0, uint32_t b1) {
    asm volatile(
        "mma.sync.aligned.m16n8k16.row.col.f32.f16.f16.f32 "
        "{%0,%1,%2,%3},{%4,%5,%6,%7},{%8,%9},{%0,%1,%2,%3};"
        : "+f"(c[0]), "+f"(c[1]), "+f"(c[2]), "+f"(c[3])
        : "r"(a[0]), "r"(a[1]), "r"(a[2]), "r"(a[3]), "r"(b0), "r"(b1));
}
__device__ __forceinline__ float exp2a(float x) {
    x = fmaxf(x, -126.0f);
    float z = x + 12582912.0f;
    uint32_t iz = __float_as_uint(z);
    float f = x - (z - 12582912.0f);
    float p = 0.0013333558f;
    p = fmaf(p, f, 0.0096180885f);
    p = fmaf(p, f, 0.0555041087f);
    p = fmaf(p, f, 0.2402265069f);
    p = fmaf(p, f, 0.6931471806f);
    p = fmaf(p, f, 1.0f);
    return __uint_as_float(__float_as_uint(p) + (iz << 23));
}
__device__ __forceinline__ void cp16(uint32_t dst, const void* src) {
    asm volatile("cp.async.ca.shared.global [%0], [%1], 16;" :: "r"(dst), "l"(src));
}
#define CP_COMMIT() asm volatile("cp.async.commit_group;" ::: "memory")
#define CP_WAIT0()  asm volatile("cp.async.wait_group 0;" ::: "memory")
#define LDSM4(d, a) \
    asm volatile("ldmatrix.sync.aligned.m8n8.x4.shared.b16 {%0,%1,%2,%3},[%4];" \
        : "=r"((d)[0]), "=r"((d)[1]), "=r"((d)[2]), "=r"((d)[3]) : "r"(a))
#define LDSM4T(d, a) \
    asm volatile("ldmatrix.sync.aligned.m8n8.x4.trans.shared.b16 {%0,%1,%2,%3},[%4];" \
        : "=r"((d)[0]), "=r"((d)[1]), "=r"((d)[2]), "=r"((d)[3]) : "r"(a))

// ======================= pre-pass conversions ===================================
#define NX4 (BB*SS*DD/4)
#define NW4 (DD*DD/4)
__global__ void cvt_all_kernel(const float* __restrict__ x,  const float* __restrict__ Wq,
                               const float* __restrict__ Wk, const float* __restrict__ Wv,
                               const float* __restrict__ Wo,
                               __half* __restrict__ xhi, __half* __restrict__ xlo,
                               __half* __restrict__ wc, __half* __restrict__ wo)
{
    int idx = blockIdx.x * blockDim.x + threadIdx.x;
    if (idx < NX4) {
        float4 v = *(const float4*)&x[(size_t)idx * 4];
        uint32_t h0, l0, h1, l1;
        split_pack_h(v.x, v.y, h0, l0);
        split_pack_h(v.z, v.w, h1, l1);
        *(uint2*)&xhi[(size_t)idx * 4] = make_uint2(h0, h1);
        *(uint2*)&xlo[(size_t)idx * 4] = make_uint2(l0, l1);
        return;
    }
    const float* src;
    __half* dst;
    int off;
    if (idx < NX4 + NW4)        { src = Wq; dst = wc;             off = idx - NX4; }
    else if (idx < NX4 + 2*NW4) { src = Wk; dst = wc + DD*DD;     off = idx - NX4 - NW4; }
    else if (idx < NX4 + 3*NW4) { src = Wv; dst = wc + 2*DD*DD;   off = idx - NX4 - 2*NW4; }
    else if (idx < NX4 + 4*NW4) { src = Wo; dst = wo;             off = idx - NX4 - 3*NW4; }
    else return;
    float4 v = *(const float4*)&src[(size_t)off * 4];
    *(uint2*)&dst[(size_t)off * 4] = make_uint2(pack_h(v.x, v.y), pack_h(v.z, v.w));
}

// ======================= RoPE table =============================================
__global__ void rope_tab_kernel(const int* __restrict__ tp, float* __restrict__ ct,
                                float* __restrict__ st)
{
    int idx = blockIdx.x * blockDim.x + threadIdx.x;
    if (idx >= BB*SS*32) return;
    int m = idx >> 5;
    int p = idx & 31;
    float inv = powf(10000.0f, -(float)(2*p) * (1.0f/64.0f));
    float freq = (float)tp[m] * inv;
    float sn, cs;
    sincosf(freq, &sn, &cs);
    ct[idx] = cs;
    st[idx] = sn;
}

// ======================= GEMM v8 (round-15, unchanged) ==========================
#define SROW 20
#define SROWB (SROW*4)
#define G5_ARR 2560
#define G5_STAGE (3*G5_ARR)
#define G5_SMEM_BYTES (2*G5_STAGE*4)   // 61440
#define CSCALE (0.125f * 1.44269504088896f)

__global__ __launch_bounds__(128, 2)
void gemm_mma8_kernel(const __half* __restrict__ Ahi, const __half* __restrict__ Alo,
                      const __half* __restrict__ Bh,
                      const float* __restrict__ ct, const float* __restrict__ st,
                      __half* __restrict__ qhi, __half* __restrict__ qlo,
                      __half* __restrict__ kkp, __half* __restrict__ vvp,
                      float* __restrict__ outp, int mode)
{
    extern __shared__ uint32_t su2[];
    const uint32_t sbase = smem_u32(su2);

    const int tid = threadIdx.x;
    const int wid = tid >> 5;
    const int lid = tid & 31;
    const int wm = wid >> 1;
    const int wn = wid & 1;
    const int r  = lid >> 2;
    const int c4 = lid & 3;
    const int i8 = lid & 7;
    const int m8 = lid >> 3;
    const int m0 = blockIdx.y * 128;

    int n0, seg;
    const __half* bp = Bh;
    if (mode == 3) {
        seg = blockIdx.x >> 3;
        n0 = (blockIdx.x & 7) * 128;
        bp += (size_t)seg * DD * DD;
    } else {
        seg = 3;
        n0 = blockIdx.x * 128;
    }
    const bool twoPass = (seg == 0 || seg == 3);

    const int prow = tid >> 2;
    const int pch  = tid & 3;

    float C[4][8][4];
    #pragma unroll
    for (int mt = 0; mt < 4; mt++)
        #pragma unroll
        for (int nt = 0; nt < 8; nt++)
            #pragma unroll
            for (int q = 0; q < 4; q++) C[mt][nt][q] = 0.f;

    auto prefetch = [&](int kt, int st2) {
        const int k0 = kt * 32;
        #pragma unroll
        for (int i = 0; i < 4; i++) {
            int row = prow + i * 32;
            uint32_t d = sbase + (uint32_t)(st2 * G5_STAGE + row * SROW + pch * 4) * 4u;
            size_t goA = (size_t)(m0 + row) * DD + k0 + pch * 8;
            size_t goB = (size_t)(n0 + row) * DD + k0 + pch * 8;
            cp16(d,                Ahi + goA);
            if (twoPass) cp16(d + G5_ARR * 4u, Alo + goA);
            cp16(d + 2u*G5_ARR*4u, bp  + goB);
        }
        CP_COMMIT();
    };

    prefetch(0, 0);

    const uint32_t aLane = (uint32_t)(wm * 64 + i8 + ((m8 & 1) << 3)) * SROWB + ((m8 & 2) << 3);
    const uint32_t bLane = (uint32_t)(wn * 64 + i8 + ((m8 & 2) << 2)) * SROWB + ((m8 & 1) << 4);

    for (int kt = 0; kt < 32; kt++) {
        CP_WAIT0();
        __syncthreads();
        if (kt < 31) prefetch(kt + 1, (kt + 1) & 1);

        const uint32_t stageB = sbase + (uint32_t)((kt & 1) * G5_STAGE) * 4u;
        const uint32_t aHiB = stageB;
        const uint32_t aLoB = stageB + G5_ARR * 4u;
        const uint32_t bB   = stageB + 2u * G5_ARR * 4u;

        #pragma unroll
        for (int kc = 0; kc < 2; kc++) {
            uint32_t bh[4][4];
            #pragma unroll
            for (int p = 0; p < 4; p++)
                LDSM4(bh[p], bB + bLane + p * (16 * SROWB) + kc * 32);
            #pragma unroll
            for (int mt = 0; mt < 4; mt++) {
                uint32_t ah[4];
                LDSM4(ah, aHiB + aLane + mt * (16 * SROWB) + kc * 32);
                #pragma unroll
                for (int p = 0; p < 4; p++) {
                    mma_f16(C[mt][2*p],   ah, bh[p][0], bh[p][1]);
                    mma_f16(C[mt][2*p+1], ah, bh[p][2], bh[p][3]);
                }
                if (twoPass) {
                    uint32_t al[4];
                    LDSM4(al, aLoB + aLane + mt * (16 * SROWB) + kc * 32);
                    #pragma unroll
                    for (int p = 0; p < 4; p++) {
                        mma_f16(C[mt][2*p],   al, bh[p][0], bh[p][1]);
                        mma_f16(C[mt][2*p+1], al, bh[p][2], bh[p][3]);
                    }
                }
            }
        }
    }

    #pragma unroll
    for (int mt = 0; mt < 4; mt++) {
        const int row0 = m0 + wm * 64 + mt * 16 + r;
        const int row1 = row0 + 8;
        #pragma unroll
        for (int nt = 0; nt < 8; nt++) {
            const int ncol = n0 + wn * 64 + nt * 8 + c4 * 2;
            float v00 = C[mt][nt][0], v01 = C[mt][nt][1];
            float v10 = C[mt][nt][2], v11 = C[mt][nt][3];
            if (seg == 3) {
                *(float2*)&outp[(size_t)row0 * DD + ncol] = make_float2(v00, v01);
                *(float2*)&outp[(size_t)row1 * DD + ncol] = make_float2(v10, v11);
            } else {
                const int h   = ncol >> 6;
                const int dk0 = ncol & 63;
                if (seg < 2) {
                    const int p = dk0 >> 1;
                    float cs0 = ct[(size_t)row0 * 32 + p], sn0 = st[(size_t)row0 * 32 + p];
                    float cs1 = ct[(size_t)row1 * 32 + p], sn1 = st[(size_t)row1 * 32 + p];
                    float t00 = cs0 * v00 - sn0 * v01;
                    float t01 = sn0 * v00 + cs0 * v01;
                    float t10 = cs1 * v10 - sn1 * v11;
                    float t11 = sn1 * v10 + cs1 * v11;
                    v00 = t00; v01 = t01; v10 = t10; v11 = t11;
                    if (seg == 0) { v00 *= CSCALE; v01 *= CSCALE; v10 *= CSCALE; v11 *= CSCALE; }
                }
                const int b0r = row0 >> 11, s0 = row0 & (SS - 1);
                const int b1r = row1 >> 11, s1 = row1 & (SS - 1);
                size_t hb0 = ((size_t)(b0r * HH + h) * SS + s0) * 32 + (dk0 >> 1);
                size_t hb1 = ((size_t)(b1r * HH + h) * SS + s1) * 32 + (dk0 >> 1);
                if (seg == 0) {
                    uint32_t h0, l0, h1, l1;
                    split_pack_h(v00, v01, h0, l0);
                    split_pack_h(v10, v11, h1, l1);
                    ((uint32_t*)qhi)[hb0] = h0;  ((uint32_t*)qlo)[hb0] = l0;
                    ((uint32_t*)qhi)[hb1] = h1;  ((uint32_t*)qlo)[hb1] = l1;
                } else if (seg == 1) {
                    ((uint32_t*)kkp)[hb0] = pack_h(v00, v01);
                    ((uint32_t*)kkp)[hb1] = pack_h(v10, v11);
                } else {
                    ((uint32_t*)vvp)[hb0] = pack_h(v00, v01);
                    ((uint32_t*)vvp)[hb1] = pack_h(v10, v11);
                }
            }
        }
    }
}

// ======================= flash attention v9: v6 with 1-pass PV ==================
#define ROWB 144
#define TILEB 18432
#define AB_Q  0
#define AB_K  (2*TILEB)
#define AB_V  (4*TILEB)
#define AB_ST (6*TILEB)
#define ATTN_SMEM_BYTES (6*TILEB + 1024)

__global__ __launch_bounds__(256)
void attn_mma9_kernel(const __half* __restrict__ qhi, const __half* __restrict__ qlo,
                      const __half* __restrict__ kk, const __half* __restrict__ vv,
                      __half* __restrict__ ohi, __half* __restrict__ olo)
{
    extern __shared__ uint32_t su[];
    const uint32_t sbase = smem_u32(su);
    float2* stats = (float2*)(su + AB_ST / 4);

    const int tid  = threadIdx.x;
    const int wid  = tid >> 5;
    const int lid  = tid & 31;
    const int wg   = wid & 3;
    const int half = wid >> 2;
    const int r    = lid >> 2;
    const int c4   = lid & 3;
    const int i8   = lid & 7;
    const int m8   = lid >> 3;
    const int bh   = blockIdx.y;
    const int qt   = gridDim.x - 1 - blockIdx.x;
    const int q0   = qt * 128;

    const __half* qhp = qhi + (size_t)bh * SS * DK;
    const __half* qlp = qlo + (size_t)bh * SS * DK;
    const __half* khp = kk  + (size_t)bh * SS * DK;
    const __half* vhp = vv  + (size_t)bh * SS * DK;

    auto tile_cp = [&](uint32_t dstB, const __half* src, int row0g) {
        #pragma unroll
        for (int t = 0; t < 4; t++) {
            int id = tid + t * 256;
            int row = id >> 3, ch = id & 7;
            cp16(dstB + row * ROWB + ch * 16, src + (size_t)(row0g + row) * DK + ch * 8);
        }
    };
    auto prefetch_kv = [&](int kt, int buf) {
        int k0 = kt * 128;
        tile_cp(sbase + AB_K + buf * TILEB, khp, k0);
        tile_cp(sbase + AB_V + buf * TILEB, vhp, k0);
        CP_COMMIT();
    };

    tile_cp(sbase + AB_Q,         qhp, q0);
    tile_cp(sbase + AB_Q + TILEB, qlp, q0);
    prefetch_kv(0, 0);

    float mrow[4], lrow[4];
    float O[2][8][4];
    #pragma unroll
    for (int i = 0; i < 4; i++) { mrow[i] = -CUDART_INF_F; lrow[i] = 0.f; }
    #pragma unroll
    for (int mb = 0; mb < 2; mb++)
        #pragma unroll
        for (int a = 0; a < 8; a++)
            #pragma unroll
            for (int b2 = 0; b2 < 4; b2++) O[mb][a][b2] = 0.f;

    const uint32_t qa_lane = sbase + AB_Q +
        (uint32_t)(wg * 32 + i8 + ((m8 & 1) << 3)) * ROWB + ((m8 & 2) << 3);
    const uint32_t kb_lane = (uint32_t)(half * 64 + i8 + ((m8 & 2) << 2)) * ROWB + ((m8 & 1) << 4);
    const uint32_t va_lane = (uint32_t)(half * 64 + i8 + ((m8 & 1) << 3)) * ROWB + ((m8 & 2) << 3);

    for (int kt = 0; kt <= qt; kt++) {
        CP_WAIT0();
        __syncthreads();
        if (kt < qt) prefetch_kv(kt + 1, (kt + 1) & 1);

        const uint32_t kbuf = sbase + AB_K + (kt & 1) * TILEB;
        const uint32_t vbuf = sbase + AB_V + (kt & 1) * TILEB;

        // ---- S = Q K^T (2-pass on Q) ----
        float Sv[2][8][4];
        #pragma unroll
        for (int mb = 0; mb < 2; mb++)
            #pragma unroll
            for (int nt = 0; nt < 8; nt++)
                #pragma unroll
                for (int q = 0; q < 4; q++) Sv[mb][nt][q] = 0.f;

        #pragma unroll
        for (int kc = 0; kc < 4; kc++) {
            uint32_t ah[2][4], al[2][4];
            LDSM4(ah[0], qa_lane + kc * 32);
            LDSM4(al[0], qa_lane + TILEB + kc * 32);
            LDSM4(ah[1], qa_lane + 16 * ROWB + kc * 32);
            LDSM4(al[1], qa_lane + TILEB + 16 * ROWB + kc * 32);
            #pragma unroll
            for (int ntp = 0; ntp < 4; ntp++) {
                uint32_t bhv[4];
                LDSM4(bhv, kbuf + kb_lane + ntp * (16 * ROWB) + kc * 32);
                #pragma unroll
                for (int mb = 0; mb < 2; mb++) {
                    mma_f16(Sv[mb][2*ntp],   ah[mb], bhv[0], bhv[1]);
                    mma_f16(Sv[mb][2*ntp+1], ah[mb], bhv[2], bhv[3]);
                    mma_f16(Sv[mb][2*ntp],   al[mb], bhv[0], bhv[1]);
                    mma_f16(Sv[mb][2*ntp+1], al[mb], bhv[2], bhv[3]);
                }
            }
        }

        // ---- causal mask ----
        if (kt == qt) {
            #pragma unroll
            for (int mb = 0; mb < 2; mb++) {
                int row0 = wg * 32 + mb * 16 + r;
                #pragma unroll
                for (int nt = 0; nt < 8; nt++) {
                    int col = half * 64 + nt * 8 + c4 * 2;
                    if (col     > row0)     Sv[mb][nt][0] = -1e30f;
                    if (col + 1 > row0)     Sv[mb][nt][1] = -1e30f;
                    if (col     > row0 + 8) Sv[mb][nt][2] = -1e30f;
                    if (col + 1 > row0 + 8) Sv[mb][nt][3] = -1e30f;
                }
            }
        }

        // ---- independent online softmax over own keys ----
        #pragma unroll
        for (int mb = 0; mb < 2; mb++) {
            #pragma unroll
            for (int hrow = 0; hrow < 2; hrow++) {
                const int ix = mb * 2 + hrow;
                float tm = -1e30f;
                #pragma unroll
                for (int nt = 0; nt < 8; nt++) {
                    tm = fmaxf(tm, Sv[mb][nt][2*hrow]);
                    tm = fmaxf(tm, Sv[mb][nt][2*hrow + 1]);
                }
                tm = fmaxf(tm, __shfl_xor_sync(0xffffffffu, tm, 1));
                tm = fmaxf(tm, __shfl_xor_sync(0xffffffffu, tm, 2));
                float mn = fmaxf(mrow[ix], tm);
                float alpha = exp2a(mrow[ix] - mn);
                float s = 0.f;
                #pragma unroll
                for (int nt = 0; nt < 8; nt++) {
                    float e0 = exp2a(Sv[mb][nt][2*hrow]     - mn);
                    float e1 = exp2a(Sv[mb][nt][2*hrow + 1] - mn);
                    Sv[mb][nt][2*hrow]     = e0;
                    Sv[mb][nt][2*hrow + 1] = e1;
                    s += e0 + e1;
                }
                s += __shfl_xor_sync(0xffffffffu, s, 1);
                s += __shfl_xor_sync(0xffffffffu, s, 2);
                lrow[ix] = lrow[ix] * alpha + s;
                mrow[ix] = mn;
                #pragma unroll
                for (int nt2 = 0; nt2 < 8; nt2++) {
                    O[mb][nt2][2*hrow]     *= alpha;
                    O[mb][nt2][2*hrow + 1] *= alpha;
                }
            }
        }

        // ---- O += P V (1-pass: P single fp16; error ~2^-11 rel, within budget) --
        #pragma unroll
        for (int kc2 = 0; kc2 < 4; kc2++) {
            uint32_t pah[2][4];
            #pragma unroll
            for (int mb = 0; mb < 2; mb++) {
                pah[mb][0] = pack_h(Sv[mb][2*kc2][0],   Sv[mb][2*kc2][1]);
                pah[mb][1] = pack_h(Sv[mb][2*kc2][2],   Sv[mb][2*kc2][3]);
                pah[mb][2] = pack_h(Sv[mb][2*kc2+1][0], Sv[mb][2*kc2+1][1]);
                pah[mb][3] = pack_h(Sv[mb][2*kc2+1][2], Sv[mb][2*kc2+1][3]);
            }
            uint32_t va0 = vbuf + va_lane + kc2 * (16 * ROWB);
            #pragma unroll
            for (int g = 0; g < 4; g++) {
                uint32_t bhv[4];
                LDSM4T(bhv, va0 + g * 32);
                #pragma unroll
                for (int mb = 0; mb < 2; mb++) {
                    mma_f16(O[mb][2*g],   pah[mb], bhv[0], bhv[1]);
                    mma_f16(O[mb][2*g+1], pah[mb], bhv[2], bhv[3]);
                }
            }
        }
    }

    __syncthreads();
    float* osm = (float*)su;
    if (half == 1) {
        #pragma unroll
        for (int mb = 0; mb < 2; mb++) {
            int srow = wg * 32 + mb * 16 + r;
            #pragma unroll
            for (int nt2 = 0; nt2 < 8; nt2++) {
                int col = nt2 * 8 + c4 * 2;
                *(float2*)&osm[(srow)     * 66 + col] = make_float2(O[mb][nt2][0], O[mb][nt2][1]);
                *(float2*)&osm[(srow + 8) * 66 + col] = make_float2(O[mb][nt2][2], O[mb][nt2][3]);
            }
            if (c4 == 0) {
                stats[srow]     = make_float2(mrow[mb*2],     lrow[mb*2]);
                stats[srow + 8] = make_float2(mrow[mb*2 + 1], lrow[mb*2 + 1]);
            }
        }
    }
    __syncthreads();
    if (half == 0) {
        const int b = bh >> 4, h = bh & 15;
        #pragma unroll
        for (int mb = 0; mb < 2; mb++) {
            int srow = wg * 32 + mb * 16 + r;
            float2 st0 = stats[srow];
            float2 st1 = stats[srow + 8];
            float nm0 = fmaxf(mrow[mb*2],     st0.x);
            float nm1 = fmaxf(mrow[mb*2 + 1], st1.x);
            float e00 = exp2a(mrow[mb*2]     - nm0), e01 = exp2a(st0.x - nm0);
            float e10 = exp2a(mrow[mb*2 + 1] - nm1), e11 = exp2a(st1.x - nm1);
            float inv0 = 1.0f / (lrow[mb*2]     * e00 + st0.y * e01);
            float inv1 = 1.0f / (lrow[mb*2 + 1] * e10 + st1.y * e11);
            const int row0g = q0 + srow;
            const int row1g = row0g + 8;
            #pragma unroll
            for (int nt2 = 0; nt2 < 8; nt2++) {
                int col = nt2 * 8 + c4 * 2;
                float2 p0 = *(float2*)&osm[(srow)     * 66 + col];
                float2 p1 = *(float2*)&osm[(srow + 8) * 66 + col];
                float v00 = (O[mb][nt2][0] * e00 + p0.x * e01) * inv0;
                float v01 = (O[mb][nt2][1] * e00 + p0.y * e01) * inv0;
                float v10 = (O[mb][nt2][2] * e10 + p1.x * e11) * inv1;
                float v11 = (O[mb][nt2][3] * e10 + p1.y * e11) * inv1;
                uint32_t h0, l0, h1, l1;
                split_pack_h(v00, v01, h0, l0);
                split_pack_h(v10, v11, h1, l1);
                int gcol = h * DK + col;
                size_t o0 = ((size_t)(b * SS + row0g) * DD + gcol) >> 1;
                size_t o1 = ((size_t)(b * SS + row1g) * DD + gcol) >> 1;
                ((uint32_t*)ohi)[o0] = h0;
                ((uint32_t*)olo)[o0] = l0;
                ((uint32_t*)ohi)[o1] = h1;
                ((uint32_t*)olo)[o1] = l1;
            }
        }
    }
}

// ---------------- launch --------------------------------------------------------
extern "C" void kernel_launch(void* const* d_in, const int* in_sizes, int n_in,
                              void* d_out, int out_size)
{
    (void)in_sizes; (void)n_in; (void)out_size;
    const float* x  = (const float*)d_in[0];
    const float* Wq = (const float*)d_in[1];
    const float* Wk = (const float*)d_in[2];
    const float* Wv = (const float*)d_in[3];
    const float* Wo = (const float*)d_in[4];
    const int*   tp = (const int*)d_in[5];
    float* out = (float*)d_out;

    float *ct, *st;
    __half *xhi, *xlo, *wc, *wo, *qhi, *qlo, *kk, *vv, *abhi, *ablo;
    cudaGetSymbolAddress((void**)&ct, g_ct);
    cudaGetSymbolAddress((void**)&st, g_st);
    cudaGetSymbolAddress((void**)&xhi, g_xhi);   cudaGetSymbolAddress((void**)&xlo, g_xlo);
    cudaGetSymbolAddress((void**)&wc, g_wc);     cudaGetSymbolAddress((void**)&wo, g_wo);
    cudaGetSymbolAddress((void**)&qhi, g_qhi);   cudaGetSymbolAddress((void**)&qlo, g_qlo);
    cudaGetSymbolAddress((void**)&kk, g_kk);     cudaGetSymbolAddress((void**)&vv, g_vv);
    cudaGetSymbolAddress((void**)&abhi, g_abhi); cudaGetSymbolAddress((void**)&ablo, g_ablo);

    cudaFuncSetAttribute(gemm_mma8_kernel, cudaFuncAttributeMaxDynamicSharedMemorySize,
                         G5_SMEM_BYTES);
    cudaFuncSetAttribute(attn_mma9_kernel, cudaFuncAttributeMaxDynamicSharedMemorySize,
                         ATTN_SMEM_BYTES);

    const int ntot = NX4 + 4 * NW4;
    cvt_all_kernel<<<(ntot + 255)/256, 256>>>(x, Wq, Wk, Wv, Wo, xhi, xlo, wc, wo);
    rope_tab_kernel<<<(BB*SS*32 + 255)/256, 256>>>(tp, ct, st);

    gemm_mma8_kernel<<<dim3(24, (BB*SS)/128), 128, G5_SMEM_BYTES>>>(
        xhi, xlo, wc, ct, st, qhi, qlo, kk, vv, nullptr, 3);

    attn_mma9_kernel<<<dim3(SS / 128, BB * HH), 256, ATTN_SMEM_BYTES>>>(
        qhi, qlo, kk, vv, abhi, ablo);

    gemm_mma8_kernel<<<dim3(8, (BB*SS)/128), 128, G5_SMEM_BYTES>>>(
        abhi, ablo, wo, ct, st, nullptr, nullptr, nullptr, nullptr, out, 2);
}

// round 17
// speedup vs baseline: 1.2497x; 1.0835x over previous
#include <cuda_runtime.h>
#include <cuda_bf16.h>
#include <cuda_fp16.h>
#include <math.h>
#include <math_constants.h>
#include <cstdint>

#define BB 2
#define SS 2048
#define DD 1024
#define HH 16
#define DK 64

// ---------------- scratch (allocation-free: __device__ globals) ----------------
__device__ float g_ct[BB*SS*32];
__device__ float g_st[BB*SS*32];
__device__ __half g_xhi[BB*SS*DD], g_xlo[BB*SS*DD];
__device__ __half g_wc[3*DD*DD];                    // Wq|Wk|Wv single fp16
__device__ __half g_wo[DD*DD];                      // Wo single fp16
__device__ __half g_qhi[BB*HH*SS*DK], g_qlo[BB*HH*SS*DK];  // headed, rope'd, *CSC
__device__ __half g_kk[BB*HH*SS*DK];                // headed, rope'd, single
__device__ __half g_vv[BB*HH*SS*DK];                // headed, single
__device__ __half g_ab[BB*SS*DD];                   // attention out, single fp16

// ======================= helpers ================================================
__device__ __forceinline__ uint32_t smem_u32(const void* p) {
    uint32_t a;
    asm("{ .reg .u64 t; cvta.to.shared.u64 t, %1; cvt.u32.u64 %0, t; }" : "=r"(a) : "l"(p));
    return a;
}
__device__ __forceinline__ uint32_t pack_h(float a, float b) {
    __half2 h = __floats2half2_rn(a, b);
    return *(uint32_t*)&h;
}
__device__ __forceinline__ void split_pack_h(float a, float b, uint32_t& hi, uint32_t& lo) {
    __half ha = __float2half_rn(a);
    __half hb = __float2half_rn(b);
    hi = (uint32_t)__half_as_ushort(ha) | ((uint32_t)__half_as_ushort(hb) << 16);
    lo = pack_h(a - __half2float(ha), b - __half2float(hb));
}
__device__ __forceinline__ void mma_f16(float c[4], const uint32_t a[4],
                                        uint32_t b0, uint32_t b1) {
    asm volatile(
        "mma.sync.aligned.m16n8k16.row.col.f32.f16.f16.f32 "
        "{%0,%1,%2,%3},{%4,%5,%6,%7},{%8,%9},{%0,%1,%2,%3};"
        : "+f"(c[0]), "+f"(c[1]), "+f"(c[2]), "+f"(c[3])
        : "r"(a[0]), "r"(a[1]), "r"(a[2]), "r"(a[3]), "r"(b0), "r"(b1));
}
__device__ __forceinline__ float exp2a(float x) {
    x = fmaxf(x, -126.0f);
    float z = x + 12582912.0f;
    uint32_t iz = __float_as_uint(z);
    float f = x - (z - 12582912.0f);
    float p = 0.0013333558f;
    p = fmaf(p, f, 0.0096180885f);
    p = fmaf(p, f, 0.0555041087f);
    p = fmaf(p, f, 0.2402265069f);
    p = fmaf(p, f, 0.6931471806f);
    p = fmaf(p, f, 1.0f);
    return __uint_as_float(__float_as_uint(p) + (iz << 23));
}
__device__ __forceinline__ void cp16(uint32_t dst, const void* src) {
    asm volatile("cp.async.ca.shared.global [%0], [%1], 16;" :: "r"(dst), "l"(src));
}
#define CP_COMMIT() asm volatile("cp.async.commit_group;" ::: "memory")
#define CP_WAIT0()  asm volatile("cp.async.wait_group 0;" ::: "memory")
#define LDSM4(d, a) \
    asm volatile("ldmatrix.sync.aligned.m8n8.x4.shared.b16 {%0,%1,%2,%3},[%4];" \
        : "=r"((d)[0]), "=r"((d)[1]), "=r"((d)[2]), "=r"((d)[3]) : "r"(a))
#define LDSM4T(d, a) \
    asm volatile("ldmatrix.sync.aligned.m8n8.x4.trans.shared.b16 {%0,%1,%2,%3},[%4];" \
        : "=r"((d)[0]), "=r"((d)[1]), "=r"((d)[2]), "=r"((d)[3]) : "r"(a))

// ======================= pre-pass conversions ===================================
#define NX4 (BB*SS*DD/4)
#define NW4 (DD*DD/4)
__global__ void cvt_all_kernel(const float* __restrict__ x,  const float* __restrict__ Wq,
                               const float* __restrict__ Wk, const float* __restrict__ Wv,
                               const float* __restrict__ Wo,
                               __half* __restrict__ xhi, __half* __restrict__ xlo,
                               __half* __restrict__ wc, __half* __restrict__ wo)
{
    int idx = blockIdx.x * blockDim.x + threadIdx.x;
    if (idx < NX4) {
        float4 v = *(const float4*)&x[(size_t)idx * 4];
        uint32_t h0, l0, h1, l1;
        split_pack_h(v.x, v.y, h0, l0);
        split_pack_h(v.z, v.w, h1, l1);
        *(uint2*)&xhi[(size_t)idx * 4] = make_uint2(h0, h1);
        *(uint2*)&xlo[(size_t)idx * 4] = make_uint2(l0, l1);
        return;
    }
    const float* src;
    __half* dst;
    int off;
    if (idx < NX4 + NW4)        { src = Wq; dst = wc;             off = idx - NX4; }
    else if (idx < NX4 + 2*NW4) { src = Wk; dst = wc + DD*DD;     off = idx - NX4 - NW4; }
    else if (idx < NX4 + 3*NW4) { src = Wv; dst = wc + 2*DD*DD;   off = idx - NX4 - 2*NW4; }
    else if (idx < NX4 + 4*NW4) { src = Wo; dst = wo;             off = idx - NX4 - 3*NW4; }
    else return;
    float4 v = *(const float4*)&src[(size_t)off * 4];
    *(uint2*)&dst[(size_t)off * 4] = make_uint2(pack_h(v.x, v.y), pack_h(v.z, v.w));
}

// ======================= RoPE table =============================================
__global__ void rope_tab_kernel(const int* __restrict__ tp, float* __restrict__ ct,
                                float* __restrict__ st)
{
    int idx = blockIdx.x * blockDim.x + threadIdx.x;
    if (idx >= BB*SS*32) return;
    int m = idx >> 5;
    int p = idx & 31;
    float inv = powf(10000.0f, -(float)(2*p) * (1.0f/64.0f));
    float freq = (float)tp[m] * inv;
    float sn, cs;
    sincosf(freq, &sn, &cs);
    ct[idx] = cs;
    st[idx] = sn;
}

// ======================= GEMM v9: 2-pass only for Q seg =========================
#define SROW 20
#define SROWB (SROW*4)
#define G5_ARR 2560
#define G5_STAGE (3*G5_ARR)
#define G5_SMEM_BYTES (2*G5_STAGE*4)   // 61440
#define CSCALE (0.125f * 1.44269504088896f)

__global__ __launch_bounds__(128, 2)
void gemm_mma9_kernel(const __half* __restrict__ Ahi, const __half* __restrict__ Alo,
                      const __half* __restrict__ Bh,
                      const float* __restrict__ ct, const float* __restrict__ st,
                      __half* __restrict__ qhi, __half* __restrict__ qlo,
                      __half* __restrict__ kkp, __half* __restrict__ vvp,
                      float* __restrict__ outp, int mode)
{
    extern __shared__ uint32_t su2[];
    const uint32_t sbase = smem_u32(su2);

    const int tid = threadIdx.x;
    const int wid = tid >> 5;
    const int lid = tid & 31;
    const int wm = wid >> 1;
    const int wn = wid & 1;
    const int r  = lid >> 2;
    const int c4 = lid & 3;
    const int i8 = lid & 7;
    const int m8 = lid >> 3;
    const int m0 = blockIdx.y * 128;

    int n0, seg;
    const __half* bp = Bh;
    if (mode == 3) {
        seg = blockIdx.x >> 3;
        n0 = (blockIdx.x & 7) * 128;
        bp += (size_t)seg * DD * DD;
    } else {
        seg = 3;
        n0 = blockIdx.x * 128;
    }
    // Only Q (stored hi/lo) needs the 2-pass A; K/V/Wo outputs tolerate 1-pass.
    const bool twoPass = (seg == 0);

    const int prow = tid >> 2;
    const int pch  = tid & 3;

    float C[4][8][4];
    #pragma unroll
    for (int mt = 0; mt < 4; mt++)
        #pragma unroll
        for (int nt = 0; nt < 8; nt++)
            #pragma unroll
            for (int q = 0; q < 4; q++) C[mt][nt][q] = 0.f;

    auto prefetch = [&](int kt, int st2) {
        const int k0 = kt * 32;
        #pragma unroll
        for (int i = 0; i < 4; i++) {
            int row = prow + i * 32;
            uint32_t d = sbase + (uint32_t)(st2 * G5_STAGE + row * SROW + pch * 4) * 4u;
            size_t goA = (size_t)(m0 + row) * DD + k0 + pch * 8;
            size_t goB = (size_t)(n0 + row) * DD + k0 + pch * 8;
            cp16(d,                Ahi + goA);
            if (twoPass) cp16(d + G5_ARR * 4u, Alo + goA);
            cp16(d + 2u*G5_ARR*4u, bp  + goB);
        }
        CP_COMMIT();
    };

    prefetch(0, 0);

    const uint32_t aLane = (uint32_t)(wm * 64 + i8 + ((m8 & 1) << 3)) * SROWB + ((m8 & 2) << 3);
    const uint32_t bLane = (uint32_t)(wn * 64 + i8 + ((m8 & 2) << 2)) * SROWB + ((m8 & 1) << 4);

    for (int kt = 0; kt < 32; kt++) {
        CP_WAIT0();
        __syncthreads();
        if (kt < 31) prefetch(kt + 1, (kt + 1) & 1);

        const uint32_t stageB = sbase + (uint32_t)((kt & 1) * G5_STAGE) * 4u;
        const uint32_t aHiB = stageB;
        const uint32_t aLoB = stageB + G5_ARR * 4u;
        const uint32_t bB   = stageB + 2u * G5_ARR * 4u;

        #pragma unroll
        for (int kc = 0; kc < 2; kc++) {
            uint32_t bh[4][4];
            #pragma unroll
            for (int p = 0; p < 4; p++)
                LDSM4(bh[p], bB + bLane + p * (16 * SROWB) + kc * 32);
            #pragma unroll
            for (int mt = 0; mt < 4; mt++) {
                uint32_t ah[4];
                LDSM4(ah, aHiB + aLane + mt * (16 * SROWB) + kc * 32);
                #pragma unroll
                for (int p = 0; p < 4; p++) {
                    mma_f16(C[mt][2*p],   ah, bh[p][0], bh[p][1]);
                    mma_f16(C[mt][2*p+1], ah, bh[p][2], bh[p][3]);
                }
                if (twoPass) {
                    uint32_t al[4];
                    LDSM4(al, aLoB + aLane + mt * (16 * SROWB) + kc * 32);
                    #pragma unroll
                    for (int p = 0; p < 4; p++) {
                        mma_f16(C[mt][2*p],   al, bh[p][0], bh[p][1]);
                        mma_f16(C[mt][2*p+1], al, bh[p][2], bh[p][3]);
                    }
                }
            }
        }
    }

    #pragma unroll
    for (int mt = 0; mt < 4; mt++) {
        const int row0 = m0 + wm * 64 + mt * 16 + r;
        const int row1 = row0 + 8;
        #pragma unroll
        for (int nt = 0; nt < 8; nt++) {
            const int ncol = n0 + wn * 64 + nt * 8 + c4 * 2;
            float v00 = C[mt][nt][0], v01 = C[mt][nt][1];
            float v10 = C[mt][nt][2], v11 = C[mt][nt][3];
            if (seg == 3) {
                *(float2*)&outp[(size_t)row0 * DD + ncol] = make_float2(v00, v01);
                *(float2*)&outp[(size_t)row1 * DD + ncol] = make_float2(v10, v11);
            } else {
                const int h   = ncol >> 6;
                const int dk0 = ncol & 63;
                if (seg < 2) {
                    const int p = dk0 >> 1;
                    float cs0 = ct[(size_t)row0 * 32 + p], sn0 = st[(size_t)row0 * 32 + p];
                    float cs1 = ct[(size_t)row1 * 32 + p], sn1 = st[(size_t)row1 * 32 + p];
                    float t00 = cs0 * v00 - sn0 * v01;
                    float t01 = sn0 * v00 + cs0 * v01;
                    float t10 = cs1 * v10 - sn1 * v11;
                    float t11 = sn1 * v10 + cs1 * v11;
                    v00 = t00; v01 = t01; v10 = t10; v11 = t11;
                    if (seg == 0) { v00 *= CSCALE; v01 *= CSCALE; v10 *= CSCALE; v11 *= CSCALE; }
                }
                const int b0r = row0 >> 11, s0 = row0 & (SS - 1);
                const int b1r = row1 >> 11, s1 = row1 & (SS - 1);
                size_t hb0 = ((size_t)(b0r * HH + h) * SS + s0) * 32 + (dk0 >> 1);
                size_t hb1 = ((size_t)(b1r * HH + h) * SS + s1) * 32 + (dk0 >> 1);
                if (seg == 0) {
                    uint32_t h0, l0, h1, l1;
                    split_pack_h(v00, v01, h0, l0);
                    split_pack_h(v10, v11, h1, l1);
                    ((uint32_t*)qhi)[hb0] = h0;  ((uint32_t*)qlo)[hb0] = l0;
                    ((uint32_t*)qhi)[hb1] = h1;  ((uint32_t*)qlo)[hb1] = l1;
                } else if (seg == 1) {
                    ((uint32_t*)kkp)[hb0] = pack_h(v00, v01);
                    ((uint32_t*)kkp)[hb1] = pack_h(v10, v11);
                } else {
                    ((uint32_t*)vvp)[hb0] = pack_h(v00, v01);
                    ((uint32_t*)vvp)[hb1] = pack_h(v10, v11);
                }
            }
        }
    }
}

// ======================= flash attention v10: single fp16 output ================
#define ROWB 144
#define TILEB 18432
#define AB_Q  0
#define AB_K  (2*TILEB)
#define AB_V  (4*TILEB)
#define AB_ST (6*TILEB)
#define ATTN_SMEM_BYTES (6*TILEB + 1024)

__global__ __launch_bounds__(256)
void attn_mma10_kernel(const __half* __restrict__ qhi, const __half* __restrict__ qlo,
                       const __half* __restrict__ kk, const __half* __restrict__ vv,
                       __half* __restrict__ oab)
{
    extern __shared__ uint32_t su[];
    const uint32_t sbase = smem_u32(su);
    float2* stats = (float2*)(su + AB_ST / 4);

    const int tid  = threadIdx.x;
    const int wid  = tid >> 5;
    const int lid  = tid & 31;
    const int wg   = wid & 3;
    const int half = wid >> 2;
    const int r    = lid >> 2;
    const int c4   = lid & 3;
    const int i8   = lid & 7;
    const int m8   = lid >> 3;
    const int bh   = blockIdx.y;
    const int qt   = gridDim.x - 1 - blockIdx.x;
    const int q0   = qt * 128;

    const __half* qhp = qhi + (size_t)bh * SS * DK;
    const __half* qlp = qlo + (size_t)bh * SS * DK;
    const __half* khp = kk  + (size_t)bh * SS * DK;
    const __half* vhp = vv  + (size_t)bh * SS * DK;

    auto tile_cp = [&](uint32_t dstB, const __half* src, int row0g) {
        #pragma unroll
        for (int t = 0; t < 4; t++) {
            int id = tid + t * 256;
            int row = id >> 3, ch = id & 7;
            cp16(dstB + row * ROWB + ch * 16, src + (size_t)(row0g + row) * DK + ch * 8);
        }
    };
    auto prefetch_kv = [&](int kt, int buf) {
        int k0 = kt * 128;
        tile_cp(sbase + AB_K + buf * TILEB, khp, k0);
        tile_cp(sbase + AB_V + buf * TILEB, vhp, k0);
        CP_COMMIT();
    };

    tile_cp(sbase + AB_Q,         qhp, q0);
    tile_cp(sbase + AB_Q + TILEB, qlp, q0);
    prefetch_kv(0, 0);

    float mrow[4], lrow[4];
    float O[2][8][4];
    #pragma unroll
    for (int i = 0; i < 4; i++) { mrow[i] = -CUDART_INF_F; lrow[i] = 0.f; }
    #pragma unroll
    for (int mb = 0; mb < 2; mb++)
        #pragma unroll
        for (int a = 0; a < 8; a++)
            #pragma unroll
            for (int b2 = 0; b2 < 4; b2++) O[mb][a][b2] = 0.f;

    const uint32_t qa_lane = sbase + AB_Q +
        (uint32_t)(wg * 32 + i8 + ((m8 & 1) << 3)) * ROWB + ((m8 & 2) << 3);
    const uint32_t kb_lane = (uint32_t)(half * 64 + i8 + ((m8 & 2) << 2)) * ROWB + ((m8 & 1) << 4);
    const uint32_t va_lane = (uint32_t)(half * 64 + i8 + ((m8 & 1) << 3)) * ROWB + ((m8 & 2) << 3);

    for (int kt = 0; kt <= qt; kt++) {
        CP_WAIT0();
        __syncthreads();
        if (kt < qt) prefetch_kv(kt + 1, (kt + 1) & 1);

        const uint32_t kbuf = sbase + AB_K + (kt & 1) * TILEB;
        const uint32_t vbuf = sbase + AB_V + (kt & 1) * TILEB;

        float Sv[2][8][4];
        #pragma unroll
        for (int mb = 0; mb < 2; mb++)
            #pragma unroll
            for (int nt = 0; nt < 8; nt++)
                #pragma unroll
                for (int q = 0; q < 4; q++) Sv[mb][nt][q] = 0.f;

        #pragma unroll
        for (int kc = 0; kc < 4; kc++) {
            uint32_t ah[2][4], al[2][4];
            LDSM4(ah[0], qa_lane + kc * 32);
            LDSM4(al[0], qa_lane + TILEB + kc * 32);
            LDSM4(ah[1], qa_lane + 16 * ROWB + kc * 32);
            LDSM4(al[1], qa_lane + TILEB + 16 * ROWB + kc * 32);
            #pragma unroll
            for (int ntp = 0; ntp < 4; ntp++) {
                uint32_t bhv[4];
                LDSM4(bhv, kbuf + kb_lane + ntp * (16 * ROWB) + kc * 32);
                #pragma unroll
                for (int mb = 0; mb < 2; mb++) {
                    mma_f16(Sv[mb][2*ntp],   ah[mb], bhv[0], bhv[1]);
                    mma_f16(Sv[mb][2*ntp+1], ah[mb], bhv[2], bhv[3]);
                    mma_f16(Sv[mb][2*ntp],   al[mb], bhv[0], bhv[1]);
                    mma_f16(Sv[mb][2*ntp+1], al[mb], bhv[2], bhv[3]);
                }
            }
        }

        if (kt == qt) {
            #pragma unroll
            for (int mb = 0; mb < 2; mb++) {
                int row0 = wg * 32 + mb * 16 + r;
                #pragma unroll
                for (int nt = 0; nt < 8; nt++) {
                    int col = half * 64 + nt * 8 + c4 * 2;
                    if (col     > row0)     Sv[mb][nt][0] = -1e30f;
                    if (col + 1 > row0)     Sv[mb][nt][1] = -1e30f;
                    if (col     > row0 + 8) Sv[mb][nt][2] = -1e30f;
                    if (col + 1 > row0 + 8) Sv[mb][nt][3] = -1e30f;
                }
            }
        }

        #pragma unroll
        for (int mb = 0; mb < 2; mb++) {
            #pragma unroll
            for (int hrow = 0; hrow < 2; hrow++) {
                const int ix = mb * 2 + hrow;
                float tm = -1e30f;
                #pragma unroll
                for (int nt = 0; nt < 8; nt++) {
                    tm = fmaxf(tm, Sv[mb][nt][2*hrow]);
                    tm = fmaxf(tm, Sv[mb][nt][2*hrow + 1]);
                }
                tm = fmaxf(tm, __shfl_xor_sync(0xffffffffu, tm, 1));
                tm = fmaxf(tm, __shfl_xor_sync(0xffffffffu, tm, 2));
                float mn = fmaxf(mrow[ix], tm);
                float alpha = exp2a(mrow[ix] - mn);
                float s = 0.f;
                #pragma unroll
                for (int nt = 0; nt < 8; nt++) {
                    float e0 = exp2a(Sv[mb][nt][2*hrow]     - mn);
                    float e1 = exp2a(Sv[mb][nt][2*hrow + 1] - mn);
                    Sv[mb][nt][2*hrow]     = e0;
                    Sv[mb][nt][2*hrow + 1] = e1;
                    s += e0 + e1;
                }
                s += __shfl_xor_sync(0xffffffffu, s, 1);
                s += __shfl_xor_sync(0xffffffffu, s, 2);
                lrow[ix] = lrow[ix] * alpha + s;
                mrow[ix] = mn;
                #pragma unroll
                for (int nt2 = 0; nt2 < 8; nt2++) {
                    O[mb][nt2][2*hrow]     *= alpha;
                    O[mb][nt2][2*hrow + 1] *= alpha;
                }
            }
        }

        #pragma unroll
        for (int kc2 = 0; kc2 < 4; kc2++) {
            uint32_t pah[2][4];
            #pragma unroll
            for (int mb = 0; mb < 2; mb++) {
                pah[mb][0] = pack_h(Sv[mb][2*kc2][0],   Sv[mb][2*kc2][1]);
                pah[mb][1] = pack_h(Sv[mb][2*kc2][2],   Sv[mb][2*kc2][3]);
                pah[mb][2] = pack_h(Sv[mb][2*kc2+1][0], Sv[mb][2*kc2+1][1]);
                pah[mb][3] = pack_h(Sv[mb][2*kc2+1][2], Sv[mb][2*kc2+1][3]);
            }
            uint32_t va0 = vbuf + va_lane + kc2 * (16 * ROWB);
            #pragma unroll
            for (int g = 0; g < 4; g++) {
                uint32_t bhv[4];
                LDSM4T(bhv, va0 + g * 32);
                #pragma unroll
                for (int mb = 0; mb < 2; mb++) {
                    mma_f16(O[mb][2*g],   pah[mb], bhv[0], bhv[1]);
                    mma_f16(O[mb][2*g+1], pah[mb], bhv[2], bhv[3]);
                }
            }
        }
    }

    __syncthreads();
    float* osm = (float*)su;
    if (half == 1) {
        #pragma unroll
        for (int mb = 0; mb < 2; mb++) {
            int srow = wg * 32 + mb * 16 + r;
            #pragma unroll
            for (int nt2 = 0; nt2 < 8; nt2++) {
                int col = nt2 * 8 + c4 * 2;
                *(float2*)&osm[(srow)     * 66 + col] = make_float2(O[mb][nt2][0], O[mb][nt2][1]);
                *(float2*)&osm[(srow + 8) * 66 + col] = make_float2(O[mb][nt2][2], O[mb][nt2][3]);
            }
            if (c4 == 0) {
                stats[srow]     = make_float2(mrow[mb*2],     lrow[mb*2]);
                stats[srow + 8] = make_float2(mrow[mb*2 + 1], lrow[mb*2 + 1]);
            }
        }
    }
    __syncthreads();
    if (half == 0) {
        const int b = bh >> 4, h = bh & 15;
        #pragma unroll
        for (int mb = 0; mb < 2; mb++) {
            int srow = wg * 32 + mb * 16 + r;
            float2 st0 = stats[srow];
            float2 st1 = stats[srow + 8];
            float nm0 = fmaxf(mrow[mb*2],     st0.x);
            float nm1 = fmaxf(mrow[mb*2 + 1], st1.x);
            float e00 = exp2a(mrow[mb*2]     - nm0), e01 = exp2a(st0.x - nm0);
            float e10 = exp2a(mrow[mb*2 + 1] - nm1), e11 = exp2a(st1.x - nm1);
            float inv0 = 1.0f / (lrow[mb*2]     * e00 + st0.y * e01);
            float inv1 = 1.0f / (lrow[mb*2 + 1] * e10 + st1.y * e11);
            const int row0g = q0 + srow;
            const int row1g = row0g + 8;
            #pragma unroll
            for (int nt2 = 0; nt2 < 8; nt2++) {
                int col = nt2 * 8 + c4 * 2;
                float2 p0 = *(float2*)&osm[(srow)     * 66 + col];
                float2 p1 = *(float2*)&osm[(srow + 8) * 66 + col];
                float v00 = (O[mb][nt2][0] * e00 + p0.x * e01) * inv0;
                float v01 = (O[mb][nt2][1] * e00 + p0.y * e01) * inv0;
                float v10 = (O[mb][nt2][2] * e10 + p1.x * e11) * inv1;
                float v11 = (O[mb][nt2][3] * e10 + p1.y * e11) * inv1;
                int gcol = h * DK + col;
                size_t o0 = ((size_t)(b * SS + row0g) * DD + gcol) >> 1;
                size_t o1 = ((size_t)(b * SS + row1g) * DD + gcol) >> 1;
                ((uint32_t*)oab)[o0] = pack_h(v00, v01);
                ((uint32_t*)oab)[o1] = pack_h(v10, v11);
            }
        }
    }
}

// ---------------- launch --------------------------------------------------------
extern "C" void kernel_launch(void* const* d_in, const int* in_sizes, int n_in,
                              void* d_out, int out_size)
{
    (void)in_sizes; (void)n_in; (void)out_size;
    const float* x  = (const float*)d_in[0];
    const float* Wq = (const float*)d_in[1];
    const float* Wk = (const float*)d_in[2];
    const float* Wv = (const float*)d_in[3];
    const float* Wo = (const float*)d_in[4];
    const int*   tp = (const int*)d_in[5];
    float* out = (float*)d_out;

    float *ct, *st;
    __half *xhi, *xlo, *wc, *wo, *qhi, *qlo, *kk, *vv, *ab;
    cudaGetSymbolAddress((void**)&ct, g_ct);
    cudaGetSymbolAddress((void**)&st, g_st);
    cudaGetSymbolAddress((void**)&xhi, g_xhi);   cudaGetSymbolAddress((void**)&xlo, g_xlo);
    cudaGetSymbolAddress((void**)&wc, g_wc);     cudaGetSymbolAddress((void**)&wo, g_wo);
    cudaGetSymbolAddress((void**)&qhi, g_qhi);   cudaGetSymbolAddress((void**)&qlo, g_qlo);
    cudaGetSymbolAddress((void**)&kk, g_kk);     cudaGetSymbolAddress((void**)&vv, g_vv);
    cudaGetSymbolAddress((void**)&ab, g_ab);

    cudaFuncSetAttribute(gemm_mma9_kernel, cudaFuncAttributeMaxDynamicSharedMemorySize,
                         G5_SMEM_BYTES);
    cudaFuncSetAttribute(attn_mma10_kernel, cudaFuncAttributeMaxDynamicSharedMemorySize,
                         ATTN_SMEM_BYTES);

    const int ntot = NX4 + 4 * NW4;
    cvt_all_kernel<<<(ntot + 255)/256, 256>>>(x, Wq, Wk, Wv, Wo, xhi, xlo, wc, wo);
    rope_tab_kernel<<<(BB*SS*32 + 255)/256, 256>>>(tp, ct, st);

    gemm_mma9_kernel<<<dim3(24, (BB*SS)/128), 128, G5_SMEM_BYTES>>>(
        xhi, xlo, wc, ct, st, qhi, qlo, kk, vv, nullptr, 3);

    attn_mma10_kernel<<<dim3(SS / 128, BB * HH), 256, ATTN_SMEM_BYTES>>>(
        qhi, qlo, kk, vv, ab);

    // Wo GEMM: 1-pass on A (ab single fp16), 1-pass on W (wo single fp16)
    gemm_mma9_kernel<<<dim3(8, (BB*SS)/128), 128, G5_SMEM_BYTES>>>(
        ab, ab, wo, ct, st, nullptr, nullptr, nullptr, nullptr, out, 2);
}